// round 13
// baseline (speedup 1.0000x reference)
#include <cuda_runtime.h>
#include <cuda_fp16.h>
#include <math.h>

#define NN 10000
#define NP 10048   // padded nodes (157 * 64)
#define NE 160000
#define W_ 256
#define H_ 512
#define EW_ 128

// Scratch (static device memory — no allocation allowed)
__device__ float g_qn[NN * H_];
__device__ float g_kn[NN * H_];
__device__ float g_vn[NN * H_];
__device__ float g_m0[NN * H_];
__device__ float g_agg[NN * H_];
__device__ uint4 g_eefh[NE * 16];              // ee fp16 A-frags
__device__ uint2 g_wf2h[8 * 3 * 8 * 8 * 32];   // Wr0..2 fp16 B-frags (perm cols, scales folded)
__device__ uint2 g_wfnh[4 * 64 * 16 * 32];     // Wq/Wk/Wv/Wm fp16 B-frags (perm cols)
__device__ uint2 g_wfph[32 * 32 * 32];         // W_post fp16 B-frags (perm cols)
__device__ uint4 g_xxfh[(NP / 16) * 512];      // LN(pre(x)) fp16 A-frags
__device__ uint4 g_xf[(NP / 16) * 512];        // raw x fp16 A-frags
__device__ uint2 g_wfpre[32 * 16 * 32];        // W_pre fp16 B-frags (natural cols, 128KB)

// Fast branch-free erf-gelu (Abramowitz-Stegun 7.1.25, |err| <= 2.5e-5 abs)
__device__ __forceinline__ float gelu_fast(float h) {
    float s = h * 0.70710678118654752f;
    float a = fabsf(s);
    float t = __fdividef(1.0f, fmaf(0.47047f, a, 1.0f));
    float p = t * fmaf(t, fmaf(t, 0.7478556f, -0.0958798f), 0.3480242f);
    float e = __expf(-s * s);
    float erfa = fmaf(-p, e, 1.0f);
    float er = copysignf(erfa, s);
    return 0.5f * h * (1.0f + er);
}

__device__ __forceinline__ unsigned packh(float a, float b) {
    __half2 h = __floats2half2_rn(a, b);
    return *(unsigned*)&h;
}

__device__ __forceinline__ void mma16(float* d, const uint4& a, const uint2& b) {
    asm volatile(
        "mma.sync.aligned.m16n8k16.row.col.f32.f16.f16.f32 "
        "{%0,%1,%2,%3},{%4,%5,%6,%7},{%8,%9},{%0,%1,%2,%3};"
        : "+f"(d[0]), "+f"(d[1]), "+f"(d[2]), "+f"(d[3])
        : "r"(a.x), "r"(a.y), "r"(a.z), "r"(a.w), "r"(b.x), "r"(b.y));
}

__device__ __forceinline__ void red4(float* p, float a, float b, float c, float d) {
    asm volatile("red.global.add.v4.f32 [%0], {%1,%2,%3,%4};"
                 :: "l"(p), "f"(a), "f"(b), "f"(c), "f"(d) : "memory");
}

// ---- mbarrier + bulk-copy helpers ----
__device__ __forceinline__ unsigned s2u(const void* p) {
    return (unsigned)__cvta_generic_to_shared(p);
}
__device__ __forceinline__ void mbar_init(unsigned mbar, unsigned cnt) {
    asm volatile("mbarrier.init.shared.b64 [%0], %1;" :: "r"(mbar), "r"(cnt) : "memory");
}
__device__ __forceinline__ void mbar_expect(unsigned mbar, unsigned bytes) {
    asm volatile("mbarrier.arrive.expect_tx.shared.b64 _, [%0], %1;"
                 :: "r"(mbar), "r"(bytes) : "memory");
}
__device__ __forceinline__ void bulk_g2s(unsigned dst, const void* src, unsigned bytes,
                                         unsigned mbar) {
    asm volatile("cp.async.bulk.shared::cta.global.mbarrier::complete_tx::bytes "
                 "[%0], [%1], %2, [%3];"
                 :: "r"(dst), "l"(src), "r"(bytes), "r"(mbar) : "memory");
}
__device__ __forceinline__ void mbar_wait(unsigned mbar, int phase) {
    asm volatile(
        "{\n\t.reg .pred P;\n\t"
        "W_%=:\n\t"
        "mbarrier.try_wait.parity.acquire.cta.shared::cta.b64 P, [%0], %1, 0x989680;\n\t"
        "@P bra.uni D_%=;\n\t"
        "bra.uni W_%=;\n\t"
        "D_%=:\n\t}"
        :: "r"(mbar), "r"(phase) : "memory");
}

// permuted physical column within a 16-col group
__device__ __forceinline__ int permcol(int nt, int gid) {
    return (nt >> 1) * 16 + (gid >> 1) * 4 + (nt & 1) * 2 + (gid & 1);
}

// ---------------------------------------------------------------------------
// Merged pre-pass:
//  [0,628):        x -> fp16 A-frags (g_xf)
//  [628,692):      W_pre -> fp16 B-frags, natural cols (g_wfpre)
//  [692,884):      Wr0..2 -> fp16 B-frags (perm, scales folded)
//  [884,1396):     Wq/Wk/Wv/Wm -> fp16 B-frags (perm)
//  [1396,1524):    W_post -> fp16 B-frags (perm)
//  [1524,6524):    ee embedding mix -> fp16 A-frags
// ---------------------------------------------------------------------------
__global__ void __launch_bounds__(256) k_wfeef(const float* __restrict__ x,
                                               const float* __restrict__ Wpre,
                                               const float* __restrict__ W0,
                                               const float* __restrict__ W1,
                                               const float* __restrict__ W2,
                                               const float* __restrict__ Wq,
                                               const float* __restrict__ Wk,
                                               const float* __restrict__ Wv,
                                               const float* __restrict__ Wm,
                                               const float* __restrict__ Wpost,
                                               const int* __restrict__ edge_attr,
                                               const float* __restrict__ edge_embed,
                                               const float* __restrict__ emb0,
                                               const float* __restrict__ emb1,
                                               const float* __restrict__ emb2,
                                               const float* __restrict__ emb3,
                                               const float* __restrict__ init0_e,
                                               const float* __restrict__ init0) {
    __shared__ float sbuf[4096];   // 16KB
    __shared__ int s_attr[128];
    int tid = threadIdx.x;
    int b = blockIdx.x;

    if (b < 628) {
        // x tile -> A-frags
        int n0 = b * 16;
        for (int idx = tid; idx < 4096; idx += 256) {
            int row = idx >> 8;
            sbuf[idx] = (n0 + row < NN) ? x[n0 * W_ + idx] : 0.f;
        }
        __syncthreads();
        unsigned* out = (unsigned*)(g_xf + (size_t)b * 512);
        for (int idx = tid; idx < 2048; idx += 256) {
            int i = idx & 3;
            int t = (idx >> 2) & 31;
            int kt = idx >> 7;
            int er = (t >> 2) + ((i & 1) << 3);
            int kc = kt * 16 + (t & 3) * 2 + ((i >> 1) << 3);
            out[idx] = packh(sbuf[er * W_ + kc], sbuf[er * W_ + kc + 1]);
        }
        return;
    }
    b -= 628;
    if (b < 64) {
        // W_pre -> B-frags natural (g_wfpre), 16384 uint2 total
        int idx = b * 256 + tid;
        int nt = idx >> 9;          // 0..31
        int kt = (idx >> 5) & 15;
        int lane = idx & 31;
        int tg = lane & 3, gid = lane >> 2;
        int col = nt * 8 + gid;
        int k0 = kt * 16 + tg * 2;
        uint2 o;
        o.x = packh(Wpre[k0 * W_ + col], Wpre[(k0 + 1) * W_ + col]);
        o.y = packh(Wpre[(k0 + 8) * W_ + col], Wpre[(k0 + 9) * W_ + col]);
        g_wfpre[(nt * 16 + kt) * 32 + lane] = o;
        return;
    }
    b -= 64;
    if (b < 192) {
        int idx = b * 256 + tid;        // 0..49151
        int m = idx / 16384;
        int j = idx & 16383;
        int nt = j >> 8;
        int kt = (j >> 5) & 7;
        int lane = j & 31;
        int tg = lane & 3, gid = lane >> 2;
        const float* W = (m == 0) ? W0 : ((m == 1) ? W1 : W2);
        float sc = __expf((m == 2) ? init0[3] : init0[2]);
        int col = permcol(nt, gid);
        int k0 = kt * 16 + tg * 2;
        uint2 o;
        o.x = packh(W[k0 * H_ + col] * sc, W[(k0 + 1) * H_ + col] * sc);
        o.y = packh(W[(k0 + 8) * H_ + col] * sc, W[(k0 + 9) * H_ + col] * sc);
        int chunk = nt >> 3, nt8 = nt & 7;
        g_wf2h[((chunk * 3 + m) * 8 + nt8) * 256 + kt * 32 + lane] = o;
        return;
    }
    b -= 192;
    if (b < 512) {
        int idx = b * 256 + tid;  // 0..131071
        int m = idx >> 15;
        int j = idx & 32767;
        int nt = j >> 9;
        int kt = (j >> 5) & 15;
        int lane = j & 31;
        int tg = lane & 3, gid = lane >> 2;
        const float* W = (m == 0) ? Wq : ((m == 1) ? Wk : ((m == 2) ? Wv : Wm));
        int col = permcol(nt, gid);
        int k0 = kt * 16 + tg * 2;
        uint2 o;
        o.x = packh(W[k0 * H_ + col], W[(k0 + 1) * H_ + col]);
        o.y = packh(W[(k0 + 8) * H_ + col], W[(k0 + 9) * H_ + col]);
        int s = m * 8 + (nt >> 3);
        g_wfnh[((s * 8 + (nt & 7)) * 16 + kt) * 32 + lane] = o;
        return;
    }
    b -= 512;
    if (b < 128) {
        int idx = b * 256 + tid;  // 0..32767
        int nt = idx >> 10;
        int kt = (idx >> 5) & 31;
        int lane = idx & 31;
        int tg = lane & 3, gid = lane >> 2;
        int col = permcol(nt, gid);
        int k0 = kt * 16 + tg * 2;
        uint2 o;
        o.x = packh(Wpost[k0 * W_ + col], Wpost[(k0 + 1) * W_ + col]);
        o.y = packh(Wpost[(k0 + 8) * W_ + col], Wpost[(k0 + 9) * W_ + col]);
        int stage = nt >> 3;
        g_wfph[((stage * 8 + (nt & 7)) * 32 + kt) * 32 + lane] = o;
        return;
    }
    b -= 128;
    // ---- ee embedding mix -> A-frags ----
    float* ee_s = sbuf;
    int e0 = b * 32;
    if (tid < 128) s_attr[tid] = edge_attr[e0 * 4 + tid];
    float ew0 = __expf(init0_e[0]), ew1 = __expf(init0_e[1]);
    float ew2 = __expf(init0_e[2]), ew3 = __expf(init0_e[3]);
    float rs = rsqrtf(ew0 + ew1 + ew2 + ew3);
    ew0 *= rs; ew1 *= rs; ew2 *= rs; ew3 *= rs;
    __syncthreads();
    for (int idx = tid; idx < 32 * EW_; idx += 256) {
        int e = idx >> 7;
        int c = idx & (EW_ - 1);
        int a0 = s_attr[e * 4 + 0], a1 = s_attr[e * 4 + 1];
        int a2 = s_attr[e * 4 + 2], a3 = s_attr[e * 4 + 3];
        float v = emb0[a0 * EW_ + c] * ew0 + emb1[a1 * EW_ + c] * ew1 +
                  emb2[a2 * EW_ + c] * ew2 + emb3[a3 * EW_ + c] * ew3;
        ee_s[idx] = 0.5f * (v + edge_embed[(e0 + e) * EW_ + c]);
    }
    __syncthreads();
    unsigned* out = (unsigned*)(g_eefh + (size_t)b * 512);
    for (int idx = tid; idx < 2048; idx += 256) {
        int i = idx & 3;
        int t = (idx >> 2) & 31;
        int kt = (idx >> 7) & 7;
        int let = idx >> 10;
        int er = (t >> 2) + ((i & 1) << 3);
        int kc = kt * 16 + (t & 3) * 2 + ((i >> 1) << 3);
        out[idx] = packh(ee_s[(let * 16 + er) * EW_ + kc],
                         ee_s[(let * 16 + er) * EW_ + kc + 1]);
    }
}

// ---------------------------------------------------------------------------
// Tensorized pre: xx = LN(x@W_pre + b_pre), 64 nodes/block, fp16 mma.
// ---------------------------------------------------------------------------
__global__ void __launch_bounds__(256, 1) k_preT(const float* __restrict__ bpre) {
    extern __shared__ char dsm[];
    uint4* a_sm = (uint4*)dsm;               // 32KB
    uint2* b_sm = (uint2*)(dsm + 32768);     // 128KB (aliased by ys after mma)
    float* ys = (float*)(dsm + 32768);       // [64][256] = 64KB
    __shared__ float s_mean[64], s_rstd[64];
    __shared__ __align__(8) unsigned long long mbar_s[2];

    int tid = threadIdx.x;
    int lane = tid & 31, wid = tid >> 5;
    int mg = wid >> 2;
    int ng = wid & 3;
    int gid = lane >> 2, tg = lane & 3;
    int blk = blockIdx.x;

    unsigned mbA = s2u(&mbar_s[0]);
    unsigned mbB = s2u(&mbar_s[1]);
    if (tid == 0) {
        mbar_init(mbA, 1);
        mbar_init(mbB, 1);
    }
    __syncthreads();
    if (tid == 0) {
        mbar_expect(mbA, 32768);
        bulk_g2s(s2u(a_sm), g_xf + (size_t)blk * 2048, 32768, mbA);
        mbar_expect(mbB, 131072);
        bulk_g2s(s2u(b_sm), g_wfpre, 65536, mbB);
        bulk_g2s(s2u(b_sm + 8192), g_wfpre + 8192, 65536, mbB);
    }

    float acc[2][8][4];
#pragma unroll
    for (int mt = 0; mt < 2; mt++)
#pragma unroll
        for (int nt = 0; nt < 8; nt++)
#pragma unroll
            for (int c = 0; c < 4; c++) acc[mt][nt][c] = 0.f;

    const uint4* aw = a_sm + mg * 1024 + lane;
    const uint2* bw = b_sm + ng * 8 * 512 + lane;

    mbar_wait(mbA, 0);
    mbar_wait(mbB, 0);

#pragma unroll 4
    for (int kt = 0; kt < 16; kt++) {
        uint4 av0 = aw[kt * 32];
        uint4 av1 = aw[512 + kt * 32];
#pragma unroll
        for (int nt = 0; nt < 8; nt++) {
            uint2 bv = bw[nt * 512 + kt * 32];
            mma16(acc[0][nt], av0, bv);
            mma16(acc[1][nt], av1, bv);
        }
    }
    __syncthreads();  // done reading b_sm; safe to alias ys

#pragma unroll
    for (int mt = 0; mt < 2; mt++) {
        int r0 = (mg * 2 + mt) * 16 + gid;
        int r1 = r0 + 8;
#pragma unroll
        for (int nt = 0; nt < 8; nt++) {
            int c = ng * 64 + nt * 8 + tg * 2;
            float2 bb = *(const float2*)(bpre + c);
            ys[r0 * W_ + c] = acc[mt][nt][0] + bb.x;
            ys[r0 * W_ + c + 1] = acc[mt][nt][1] + bb.y;
            ys[r1 * W_ + c] = acc[mt][nt][2] + bb.x;
            ys[r1 * W_ + c + 1] = acc[mt][nt][3] + bb.y;
        }
    }
    __syncthreads();

#pragma unroll
    for (int rr = 0; rr < 8; rr++) {
        int row = wid * 8 + rr;
        float s = 0.f;
#pragma unroll
        for (int m = 0; m < W_ / 32; m++) s += ys[row * W_ + lane + 32 * m];
#pragma unroll
        for (int off = 16; off > 0; off >>= 1) s += __shfl_xor_sync(0xffffffffu, s, off);
        float mean = s * (1.0f / W_);
        float v = 0.f;
#pragma unroll
        for (int m = 0; m < W_ / 32; m++) {
            float d = ys[row * W_ + lane + 32 * m] - mean;
            v += d * d;
        }
#pragma unroll
        for (int off = 16; off > 0; off >>= 1) v += __shfl_xor_sync(0xffffffffu, v, off);
        if (lane == 0) {
            s_mean[row] = mean;
            s_rstd[row] = rsqrtf(v * (1.0f / W_) + 1e-5f);
        }
    }
    __syncthreads();

    unsigned* out = (unsigned*)(g_xxfh + (size_t)blk * 2048);
    for (int idx = tid; idx < 8192; idx += 256) {
        int w = idx & 2047;
        int tile = idx >> 11;
        int i = w & 3;
        int t = (w >> 2) & 31;
        int kt = w >> 7;
        int er = (t >> 2) + ((i & 1) << 3);
        int row = tile * 16 + er;
        int kc = kt * 16 + (t & 3) * 2 + ((i >> 1) << 3);
        float mean = s_mean[row], rstd = s_rstd[row];
        out[idx] = packh((ys[row * W_ + kc] - mean) * rstd,
                         (ys[row * W_ + kc + 1] - mean) * rstd);
    }
}

// ---------------------------------------------------------------------------
// fp16 node projections: 64 nodes/block, 32 passes, float4 epilogue stores.
// ---------------------------------------------------------------------------
__global__ void __launch_bounds__(256, 2) k_projz(const float* __restrict__ bq,
                                                  const float* __restrict__ bk,
                                                  const float* __restrict__ bv,
                                                  const float* __restrict__ bm,
                                                  const float* __restrict__ br0,
                                                  const float* __restrict__ br1,
                                                  const float* __restrict__ br2,
                                                  const float* __restrict__ init0) {
    extern __shared__ char dsm[];
    uint4* a_sm = (uint4*)dsm;               // 32KB
    uint2* b_sm = (uint2*)(dsm + 32768);     // 2 x 32KB
    __shared__ __align__(8) unsigned long long mbar_s[3];

    int tid = threadIdx.x;
    int lane = tid & 31, wid = tid >> 5;
    int mg = wid >> 2;
    int ng = wid & 3;
    int gid = lane >> 2, tg = lane & 3;
    int blk = blockIdx.x;

    unsigned mbA = s2u(&mbar_s[0]);
    unsigned mb0 = s2u(&mbar_s[1]);
    unsigned mb1 = s2u(&mbar_s[2]);
    if (tid == 0) {
        mbar_init(mbA, 1);
        mbar_init(mb0, 1);
        mbar_init(mb1, 1);
    }
    float s_e = __expf(init0[2]);
    float s_v = __expf(init0[3]);
    __syncthreads();

    if (tid == 0) {
        mbar_expect(mbA, 32768);
        bulk_g2s(s2u(a_sm), g_xxfh + (size_t)blk * 2048, 32768, mbA);
        mbar_expect(mb0, 32768);
        bulk_g2s(s2u(b_sm), g_wfnh, 32768, mb0);
        mbar_expect(mb1, 32768);
        bulk_g2s(s2u(b_sm + 4096), g_wfnh + 4096, 32768, mb1);
    }

    {
        int r0 = blk * 64;
        float4 z = make_float4(0.f, 0.f, 0.f, 0.f);
        for (int i = tid; i < 64 * (H_ / 4); i += 256) {
            int r = r0 + (i >> 7);
            if (r < NN) *(float4*)(g_agg + (size_t)r * H_ + ((i & 127) << 2)) = z;
        }
    }

    const uint4* aw = a_sm + mg * 1024 + lane;
    const uint2* bw = b_sm + (ng * 2) * 512 + lane;

    mbar_wait(mbA, 0);
    int ph0 = 0, ph1 = 0;

#pragma unroll 1
    for (int s = 0; s < 32; s++) {
        int buf = s & 1;
        if (buf == 0) { mbar_wait(mb0, ph0); ph0 ^= 1; }
        else          { mbar_wait(mb1, ph1); ph1 ^= 1; }

        float acc[2][2][4];
#pragma unroll
        for (int mt = 0; mt < 2; mt++)
#pragma unroll
            for (int nt = 0; nt < 2; nt++)
#pragma unroll
                for (int c = 0; c < 4; c++) acc[mt][nt][c] = 0.f;

#pragma unroll 4
        for (int kt = 0; kt < 16; kt++) {
            uint4 av0 = aw[kt * 32];
            uint4 av1 = aw[512 + kt * 32];
            uint2 bv0 = bw[buf * 4096 + kt * 32];
            uint2 bv1 = bw[buf * 4096 + 512 + kt * 32];
            mma16(acc[0][0], av0, bv0);
            mma16(acc[0][1], av0, bv1);
            mma16(acc[1][0], av1, bv0);
            mma16(acc[1][1], av1, bv1);
        }
        __syncthreads();
        if (tid == 0 && s + 2 < 32) {
            if (buf == 0) { mbar_expect(mb0, 32768); bulk_g2s(s2u(b_sm), g_wfnh + (size_t)(s + 2) * 4096, 32768, mb0); }
            else          { mbar_expect(mb1, 32768); bulk_g2s(s2u(b_sm + 4096), g_wfnh + (size_t)(s + 2) * 4096, 32768, mb1); }
        }

        int m = s >> 3, cc = s & 7;
        const float* bmain = (m == 0) ? bq : ((m == 1) ? bk : ((m == 2) ? bv : bm));
        const float* badd  = (m == 0) ? br0 : ((m == 1) ? br1 : br2);
        float scale = (m < 2) ? s_e : s_v;
        float* dst = (m == 0) ? g_qn : ((m == 1) ? g_kn : ((m == 2) ? g_vn : g_m0));
        int col = cc * 64 + ng * 16 + tg * 4;
        float4 bb = *(const float4*)(bmain + col);
        if (m < 3) {
            float4 b2 = *(const float4*)(badd + col);
            bb = make_float4(bb.x + b2.x * scale, bb.y + b2.y * scale,
                             bb.z + b2.z * scale, bb.w + b2.w * scale);
        }
#pragma unroll
        for (int mt = 0; mt < 2; mt++) {
            int r0 = blk * 64 + mg * 32 + mt * 16 + gid;
            int r1 = r0 + 8;
            float4 o0 = make_float4(acc[mt][0][0] + bb.x, acc[mt][0][1] + bb.y,
                                    acc[mt][1][0] + bb.z, acc[mt][1][1] + bb.w);
            float4 o1 = make_float4(acc[mt][0][2] + bb.x, acc[mt][0][3] + bb.y,
                                    acc[mt][1][2] + bb.z, acc[mt][1][3] + bb.w);
            if (m == 3) {
                o0 = make_float4(gelu_fast(o0.x), gelu_fast(o0.y), gelu_fast(o0.z), gelu_fast(o0.w));
                o1 = make_float4(gelu_fast(o1.x), gelu_fast(o1.y), gelu_fast(o1.z), gelu_fast(o1.w));
            }
            if (r0 < NN) *(float4*)(dst + (size_t)r0 * H_ + col) = o0;
            if (r1 < NN) *(float4*)(dst + (size_t)r1 * H_ + col) = o1;
        }
    }
}

// ---------------------------------------------------------------------------
// fp16 edge kernel: 128 edges/block, 512 threads (4 mg x 4 ng).
// All q/k/v gathers issued BEFORE the B-wait so their L2 latency hides under
// the full mma section. One __syncthreads per chunk.
// ---------------------------------------------------------------------------
__global__ void __launch_bounds__(512) k_edge(const int* __restrict__ edge_index,
                                              const float* __restrict__ init0) {
    extern __shared__ char dsm[];
    uint4* a_sm = (uint4*)dsm;               // 32KB
    uint2* b_sm = (uint2*)(dsm + 32768);     // 2 x 48KB
    __shared__ int s_src[128], s_dst[128];
    __shared__ float p_buf[2][4][128];
    __shared__ __align__(8) unsigned long long mbar_s[3];

    int tid = threadIdx.x;
    int lane = tid & 31, wid = tid >> 5;
    int mg = wid >> 2;
    int ng = wid & 3;
    int gid = lane >> 2, tg = lane & 3;
    int e0 = blockIdx.x * 128;

    unsigned mbA = s2u(&mbar_s[0]);
    unsigned mb0 = s2u(&mbar_s[1]);
    unsigned mb1 = s2u(&mbar_s[2]);

    if (tid < 128) {
        s_src[tid] = edge_index[e0 + tid];
        s_dst[tid] = edge_index[NE + e0 + tid];
    }
    if (tid == 0) {
        mbar_init(mbA, 1);
        mbar_init(mb0, 1);
        mbar_init(mb1, 1);
    }
    float c0 = init0[0] * 0.125f;
    float c1 = init0[1];
    __syncthreads();

    if (tid == 0) {
        mbar_expect(mbA, 32768);
        bulk_g2s(s2u(a_sm), g_eefh + (size_t)blockIdx.x * 2048, 32768, mbA);
        mbar_expect(mb0, 49152);
        bulk_g2s(s2u(b_sm), g_wf2h, 49152, mb0);
        mbar_expect(mb1, 49152);
        bulk_g2s(s2u(b_sm + 6144), g_wf2h + 6144, 49152, mb1);
    }

    int rd0[2], rd1[2], rs0[2], rs1[2];
#pragma unroll
    for (int mt = 0; mt < 2; mt++) {
        int el = mg * 32 + mt * 16 + gid;
        rd0[mt] = s_dst[el];
        rd1[mt] = s_dst[el + 8];
        rs0[mt] = s_src[el];
        rs1[mt] = s_src[el + 8];
    }

    const uint4* aw = a_sm + mg * 512 + lane;
    const uint2* bw = b_sm + (ng * 2) * 256 + lane;

    mbar_wait(mbA, 0);
    int ph0 = 0, ph1 = 0;

#pragma unroll 1
    for (int chunk = 0; chunk < 8; chunk++) {
        float acc[3][2][2][4];
#pragma unroll
        for (int m = 0; m < 3; m++)
#pragma unroll
            for (int mt = 0; mt < 2; mt++)
#pragma unroll
                for (int nt = 0; nt < 2; nt++)
#pragma unroll
                    for (int c = 0; c < 4; c++) acc[m][mt][nt][c] = 0.f;

        int colbase = chunk * 64 + ng * 16 + tg * 4;
        int bufbase = (chunk & 1) * 6144;
        int pb = chunk & 1;

        // all gathers issued up front: full mma section hides their latency
        float4 qv[2][2], kv[2][2], vv[2][2];
#pragma unroll
        for (int mt = 0; mt < 2; mt++) {
            qv[mt][0] = *(const float4*)(g_qn + (size_t)rd0[mt] * H_ + colbase);
            qv[mt][1] = *(const float4*)(g_qn + (size_t)rd1[mt] * H_ + colbase);
            kv[mt][0] = *(const float4*)(g_kn + (size_t)rs0[mt] * H_ + colbase);
            kv[mt][1] = *(const float4*)(g_kn + (size_t)rs1[mt] * H_ + colbase);
            vv[mt][0] = *(const float4*)(g_vn + (size_t)rs0[mt] * H_ + colbase);
            vv[mt][1] = *(const float4*)(g_vn + (size_t)rs1[mt] * H_ + colbase);
        }

        if ((chunk & 1) == 0) { mbar_wait(mb0, ph0); ph0 ^= 1; }
        else                  { mbar_wait(mb1, ph1); ph1 ^= 1; }

#pragma unroll
        for (int kt = 0; kt < 8; kt++) {
            uint4 av0 = aw[kt * 32];
            uint4 av1 = aw[256 + kt * 32];
            uint2 bv[3][2];
#pragma unroll
            for (int m = 0; m < 3; m++)
#pragma unroll
                for (int nt = 0; nt < 2; nt++)
                    bv[m][nt] = bw[bufbase + (m * 8 + nt) * 256 + kt * 32];
#pragma unroll
            for (int m = 0; m < 3; m++)
#pragma unroll
                for (int nt = 0; nt < 2; nt++) {
                    mma16(acc[m][0][nt], av0, bv[m][nt]);
                    mma16(acc[m][1][nt], av1, bv[m][nt]);
                }
        }

        float p[2][2];
#pragma unroll
        for (int mt = 0; mt < 2; mt++) {
            p[mt][0] = (qv[mt][0].x + acc[0][mt][0][0]) * (kv[mt][0].x + acc[1][mt][0][0])
                     + (qv[mt][0].y + acc[0][mt][0][1]) * (kv[mt][0].y + acc[1][mt][0][1])
                     + (qv[mt][0].z + acc[0][mt][1][0]) * (kv[mt][0].z + acc[1][mt][1][0])
                     + (qv[mt][0].w + acc[0][mt][1][1]) * (kv[mt][0].w + acc[1][mt][1][1]);
            p[mt][1] = (qv[mt][1].x + acc[0][mt][0][2]) * (kv[mt][1].x + acc[1][mt][0][2])
                     + (qv[mt][1].y + acc[0][mt][0][3]) * (kv[mt][1].y + acc[1][mt][0][3])
                     + (qv[mt][1].z + acc[0][mt][1][2]) * (kv[mt][1].z + acc[1][mt][1][2])
                     + (qv[mt][1].w + acc[0][mt][1][3]) * (kv[mt][1].w + acc[1][mt][1][3]);
        }
#pragma unroll
        for (int off = 1; off <= 2; off <<= 1) {
            p[0][0] += __shfl_xor_sync(0xffffffffu, p[0][0], off);
            p[0][1] += __shfl_xor_sync(0xffffffffu, p[0][1], off);
            p[1][0] += __shfl_xor_sync(0xffffffffu, p[1][0], off);
            p[1][1] += __shfl_xor_sync(0xffffffffu, p[1][1], off);
        }
        if (tg == 0) {
#pragma unroll
            for (int mt = 0; mt < 2; mt++) {
                int el = mg * 32 + mt * 16 + gid;
                p_buf[pb][ng][el] = p[mt][0];
                p_buf[pb][ng][el + 8] = p[mt][1];
            }
        }
        __syncthreads();   // pbuf write->read; also all warps done with B buf
        if (tid == 0 && chunk < 6) {
            if ((chunk & 1) == 0) { mbar_expect(mb0, 49152); bulk_g2s(s2u(b_sm), g_wf2h + (size_t)(chunk + 2) * 6144, 49152, mb0); }
            else                  { mbar_expect(mb1, 49152); bulk_g2s(s2u(b_sm + 6144), g_wf2h + (size_t)(chunk + 2) * 6144, 49152, mb1); }
        }

#pragma unroll
        for (int mt = 0; mt < 2; mt++) {
            int el = mg * 32 + mt * 16 + gid;
            float sum0 = p_buf[pb][0][el] + p_buf[pb][1][el] + p_buf[pb][2][el] + p_buf[pb][3][el];
            float sum1 = p_buf[pb][0][el + 8] + p_buf[pb][1][el + 8] + p_buf[pb][2][el + 8] + p_buf[pb][3][el + 8];
            float att0 = __expf(sum0 * c0 + c1);
            float att1 = __expf(sum1 * c0 + c1);
            red4(g_agg + (size_t)rd0[mt] * H_ + colbase,
                 gelu_fast(vv[mt][0].x + acc[2][mt][0][0]) * att0,
                 gelu_fast(vv[mt][0].y + acc[2][mt][0][1]) * att0,
                 gelu_fast(vv[mt][0].z + acc[2][mt][1][0]) * att0,
                 gelu_fast(vv[mt][0].w + acc[2][mt][1][1]) * att0);
            red4(g_agg + (size_t)rd1[mt] * H_ + colbase,
                 gelu_fast(vv[mt][1].x + acc[2][mt][0][2]) * att1,
                 gelu_fast(vv[mt][1].y + acc[2][mt][0][3]) * att1,
                 gelu_fast(vv[mt][1].z + acc[2][mt][1][2]) * att1,
                 gelu_fast(vv[mt][1].w + acc[2][mt][1][3]) * att1);
        }
    }
}

// ---------------------------------------------------------------------------
// fp16 post kernel: out = x + (m0+agg) @ W_post + b_post. float4 A-build.
// ---------------------------------------------------------------------------
__global__ void __launch_bounds__(256) k_post(const float* __restrict__ x,
                                              const float* __restrict__ bp,
                                              float* __restrict__ out) {
    extern __shared__ char dsm[];
    uint4* a_sm = (uint4*)dsm;               // 64KB
    uint2* b_sm = (uint2*)(dsm + 65536);     // 2 x 64KB
    __shared__ __align__(8) unsigned long long mbar_s[2];

    int tid = threadIdx.x;
    int lane = tid & 31, wid = tid >> 5;
    int mg = wid >> 2;
    int ng = wid & 3;
    int gid = lane >> 2, tg = lane & 3;
    int blk = blockIdx.x;

    unsigned mb0 = s2u(&mbar_s[0]);
    unsigned mb1 = s2u(&mbar_s[1]);
    if (tid == 0) {
        mbar_init(mb0, 1);
        mbar_init(mb1, 1);
    }
    __syncthreads();
    if (tid == 0) {
        mbar_expect(mb0, 65536);
        bulk_g2s(s2u(b_sm), g_wfph, 65536, mb0);
        mbar_expect(mb1, 65536);
        bulk_g2s(s2u(b_sm + 8192), g_wfph + 8192, 65536, mb1);
    }

    {
        unsigned* aword = (unsigned*)a_sm;
        for (int idx = tid; idx < 8192; idx += 256) {
            int rl = idx >> 7;
            int c4 = (idx & 127) << 2;
            int row = blk * 64 + rl;
            float4 f = make_float4(0.f, 0.f, 0.f, 0.f);
            if (row < NN) {
                float4 m4 = *(const float4*)(g_m0 + (size_t)row * H_ + c4);
                float4 a4 = *(const float4*)(g_agg + (size_t)row * H_ + c4);
                f = make_float4(m4.x + a4.x, m4.y + a4.y, m4.z + a4.z, m4.w + a4.w);
            }
            int mt = rl >> 4;
            int er = rl & 15;
            int kt = c4 >> 4;
            int i = (er >> 3) | (((c4 >> 3) & 1) << 1);
            int tb = (er & 7) * 4 + ((c4 >> 1) & 3);
            int base = ((mt * 32 + kt) * 32 + tb) * 4 + i;
            aword[base] = packh(f.x, f.y);
            aword[base + 4] = packh(f.z, f.w);
        }
    }
    __syncthreads();

    const uint4* aw = a_sm + mg * 2048 + lane;
    const uint2* bw = b_sm + (ng * 2) * 1024 + lane;
    int ph0 = 0, ph1 = 0;

#pragma unroll 1
    for (int s = 0; s < 4; s++) {
        int buf = s & 1;
        if (buf == 0) { mbar_wait(mb0, ph0); ph0 ^= 1; }
        else          { mbar_wait(mb1, ph1); ph1 ^= 1; }

        float acc[2][2][4];
#pragma unroll
        for (int mt = 0; mt < 2; mt++)
#pragma unroll
            for (int nt = 0; nt < 2; nt++)
#pragma unroll
                for (int c = 0; c < 4; c++) acc[mt][nt][c] = 0.f;

#pragma unroll 4
        for (int kt = 0; kt < 32; kt++) {
            uint4 av0 = aw[kt * 32];
            uint4 av1 = aw[1024 + kt * 32];
            uint2 bv0 = bw[buf * 8192 + kt * 32];
            uint2 bv1 = bw[buf * 8192 + 1024 + kt * 32];
            mma16(acc[0][0], av0, bv0);
            mma16(acc[0][1], av0, bv1);
            mma16(acc[1][0], av1, bv0);
            mma16(acc[1][1], av1, bv1);
        }
        __syncthreads();
        if (tid == 0 && s + 2 < 4) {
            if (buf == 0) { mbar_expect(mb0, 65536); bulk_g2s(s2u(b_sm), g_wfph + (size_t)(s + 2) * 8192, 65536, mb0); }
            else          { mbar_expect(mb1, 65536); bulk_g2s(s2u(b_sm + 8192), g_wfph + (size_t)(s + 2) * 8192, 65536, mb1); }
        }

        int col = s * 64 + ng * 16 + tg * 4;
        float4 bb = *(const float4*)(bp + col);
#pragma unroll
        for (int mt = 0; mt < 2; mt++) {
            int r0 = blk * 64 + mg * 32 + mt * 16 + gid;
            int r1 = r0 + 8;
            if (r0 < NN) {
                float4 xx0 = *(const float4*)(x + (size_t)r0 * W_ + col);
                *(float4*)(out + (size_t)r0 * W_ + col) =
                    make_float4(xx0.x + acc[mt][0][0] + bb.x, xx0.y + acc[mt][0][1] + bb.y,
                                xx0.z + acc[mt][1][0] + bb.z, xx0.w + acc[mt][1][1] + bb.w);
            }
            if (r1 < NN) {
                float4 xx1 = *(const float4*)(x + (size_t)r1 * W_ + col);
                *(float4*)(out + (size_t)r1 * W_ + col) =
                    make_float4(xx1.x + acc[mt][0][2] + bb.x, xx1.y + acc[mt][0][3] + bb.y,
                                xx1.z + acc[mt][1][2] + bb.z, xx1.w + acc[mt][1][3] + bb.w);
            }
        }
    }
}

extern "C" void kernel_launch(void* const* d_in, const int* in_sizes, int n_in,
                              void* d_out, int out_size) {
    const float* x          = (const float*)d_in[0];
    const int*   edge_index = (const int*)d_in[1];
    const int*   edge_attr  = (const int*)d_in[2];
    const float* edge_embed = (const float*)d_in[3];
    const float* emb0       = (const float*)d_in[4];
    const float* emb1       = (const float*)d_in[5];
    const float* emb2       = (const float*)d_in[6];
    const float* emb3       = (const float*)d_in[7];
    const float* init0_e    = (const float*)d_in[8];
    const float* init0      = (const float*)d_in[9];
    const float* W_pre      = (const float*)d_in[10];
    const float* b_pre      = (const float*)d_in[11];
    const float* W_msg0     = (const float*)d_in[12];
    const float* b_msg0     = (const float*)d_in[13];
    const float* W_q        = (const float*)d_in[14];
    const float* b_q        = (const float*)d_in[15];
    const float* W_k        = (const float*)d_in[16];
    const float* b_k        = (const float*)d_in[17];
    const float* W_v        = (const float*)d_in[18];
    const float* b_v        = (const float*)d_in[19];
    const float* W_r0       = (const float*)d_in[20];
    const float* b_r0       = (const float*)d_in[21];
    const float* W_r1       = (const float*)d_in[22];
    const float* b_r1       = (const float*)d_in[23];
    const float* W_r2       = (const float*)d_in[24];
    const float* b_r2       = (const float*)d_in[25];
    const float* W_post     = (const float*)d_in[26];
    const float* b_post     = (const float*)d_in[27];
    float* out = (float*)d_out;

    cudaFuncSetAttribute(k_edge, cudaFuncAttributeMaxDynamicSharedMemorySize, 131072);
    cudaFuncSetAttribute(k_projz, cudaFuncAttributeMaxDynamicSharedMemorySize, 98304);
    cudaFuncSetAttribute(k_post, cudaFuncAttributeMaxDynamicSharedMemorySize, 196608);
    cudaFuncSetAttribute(k_preT, cudaFuncAttributeMaxDynamicSharedMemorySize, 163840);

    k_wfeef<<<1524 + NE / 32, 256>>>(x, W_pre,
                                     W_r0, W_r1, W_r2, W_q, W_k, W_v, W_msg0, W_post,
                                     edge_attr, edge_embed,
                                     emb0, emb1, emb2, emb3, init0_e, init0);
    k_preT<<<NP / 64, 256, 163840>>>(b_pre);
    k_projz<<<NP / 64, 256, 98304>>>(b_q, b_k, b_v, b_msg0, b_r0, b_r1, b_r2, init0);
    k_edge<<<NE / 128, 512, 131072>>>(edge_index, init0);
    k_post<<<NP / 64, 256, 196608>>>(x, b_post, out);
}

// round 14
// speedup vs baseline: 1.0971x; 1.0971x over previous
#include <cuda_runtime.h>
#include <cuda_fp16.h>
#include <math.h>

#define NN 10000
#define NP 10048   // padded nodes (157 * 64)
#define NE 160000
#define W_ 256
#define H_ 512
#define EW_ 128

// Scratch (static device memory — no allocation allowed)
__device__ float g_qn[NN * H_];
__device__ float g_kn[NN * H_];
__device__ float g_vn[NN * H_];
__device__ float g_m0[NN * H_];
__device__ float g_agg[NN * H_];
__device__ uint4 g_eefh[NE * 16];              // ee fp16 A-frags
__device__ uint2 g_wf2h[8 * 3 * 8 * 8 * 32];   // Wr0..2 fp16 B-frags (perm cols, scales folded)
__device__ uint2 g_wfnh[4 * 64 * 16 * 32];     // Wq/Wk/Wv/Wm fp16 B-frags (perm cols)
__device__ uint2 g_wfph[32 * 32 * 32];         // W_post fp16 B-frags (perm cols)
__device__ uint4 g_xxfh[(NP / 16) * 512];      // LN(pre(x)) fp16 A-frags
__device__ uint4 g_xf[(NP / 16) * 512];        // raw x fp16 A-frags
__device__ uint2 g_wfpre[32 * 16 * 32];        // W_pre fp16 B-frags (natural cols, 128KB)

// Fast branch-free erf-gelu (Abramowitz-Stegun 7.1.25, |err| <= 2.5e-5 abs)
__device__ __forceinline__ float gelu_fast(float h) {
    float s = h * 0.70710678118654752f;
    float a = fabsf(s);
    float t = __fdividef(1.0f, fmaf(0.47047f, a, 1.0f));
    float p = t * fmaf(t, fmaf(t, 0.7478556f, -0.0958798f), 0.3480242f);
    float e = __expf(-s * s);
    float erfa = fmaf(-p, e, 1.0f);
    float er = copysignf(erfa, s);
    return 0.5f * h * (1.0f + er);
}

__device__ __forceinline__ unsigned packh(float a, float b) {
    __half2 h = __floats2half2_rn(a, b);
    return *(unsigned*)&h;
}

__device__ __forceinline__ void mma16(float* d, const uint4& a, const uint2& b) {
    asm volatile(
        "mma.sync.aligned.m16n8k16.row.col.f32.f16.f16.f32 "
        "{%0,%1,%2,%3},{%4,%5,%6,%7},{%8,%9},{%0,%1,%2,%3};"
        : "+f"(d[0]), "+f"(d[1]), "+f"(d[2]), "+f"(d[3])
        : "r"(a.x), "r"(a.y), "r"(a.z), "r"(a.w), "r"(b.x), "r"(b.y));
}

__device__ __forceinline__ void red4(float* p, float a, float b, float c, float d) {
    asm volatile("red.global.add.v4.f32 [%0], {%1,%2,%3,%4};"
                 :: "l"(p), "f"(a), "f"(b), "f"(c), "f"(d) : "memory");
}

// ---- mbarrier + bulk-copy helpers ----
__device__ __forceinline__ unsigned s2u(const void* p) {
    return (unsigned)__cvta_generic_to_shared(p);
}
__device__ __forceinline__ void mbar_init(unsigned mbar, unsigned cnt) {
    asm volatile("mbarrier.init.shared.b64 [%0], %1;" :: "r"(mbar), "r"(cnt) : "memory");
}
__device__ __forceinline__ void mbar_expect(unsigned mbar, unsigned bytes) {
    asm volatile("mbarrier.arrive.expect_tx.shared.b64 _, [%0], %1;"
                 :: "r"(mbar), "r"(bytes) : "memory");
}
__device__ __forceinline__ void bulk_g2s(unsigned dst, const void* src, unsigned bytes,
                                         unsigned mbar) {
    asm volatile("cp.async.bulk.shared::cta.global.mbarrier::complete_tx::bytes "
                 "[%0], [%1], %2, [%3];"
                 :: "r"(dst), "l"(src), "r"(bytes), "r"(mbar) : "memory");
}
__device__ __forceinline__ void mbar_wait(unsigned mbar, int phase) {
    asm volatile(
        "{\n\t.reg .pred P;\n\t"
        "W_%=:\n\t"
        "mbarrier.try_wait.parity.acquire.cta.shared::cta.b64 P, [%0], %1, 0x989680;\n\t"
        "@P bra.uni D_%=;\n\t"
        "bra.uni W_%=;\n\t"
        "D_%=:\n\t}"
        :: "r"(mbar), "r"(phase) : "memory");
}

// permuted physical column within a 16-col group
__device__ __forceinline__ int permcol(int nt, int gid) {
    return (nt >> 1) * 16 + (gid >> 1) * 4 + (nt & 1) * 2 + (gid & 1);
}

// ---------------------------------------------------------------------------
// Merged pre-pass:
//  [0,628):        x -> fp16 A-frags (g_xf)
//  [628,692):      W_pre -> fp16 B-frags, natural cols (g_wfpre)
//  [692,884):      Wr0..2 -> fp16 B-frags (perm, scales folded)
//  [884,1396):     Wq/Wk/Wv/Wm -> fp16 B-frags (perm)
//  [1396,1524):    W_post -> fp16 B-frags (perm)
//  [1524,6524):    ee embedding mix -> fp16 A-frags
// ---------------------------------------------------------------------------
__global__ void __launch_bounds__(256) k_wfeef(const float* __restrict__ x,
                                               const float* __restrict__ Wpre,
                                               const float* __restrict__ W0,
                                               const float* __restrict__ W1,
                                               const float* __restrict__ W2,
                                               const float* __restrict__ Wq,
                                               const float* __restrict__ Wk,
                                               const float* __restrict__ Wv,
                                               const float* __restrict__ Wm,
                                               const float* __restrict__ Wpost,
                                               const int* __restrict__ edge_attr,
                                               const float* __restrict__ edge_embed,
                                               const float* __restrict__ emb0,
                                               const float* __restrict__ emb1,
                                               const float* __restrict__ emb2,
                                               const float* __restrict__ emb3,
                                               const float* __restrict__ init0_e,
                                               const float* __restrict__ init0) {
    __shared__ float sbuf[4096];   // 16KB
    __shared__ int s_attr[128];
    int tid = threadIdx.x;
    int b = blockIdx.x;

    if (b < 628) {
        // x tile -> A-frags
        int n0 = b * 16;
        for (int idx = tid; idx < 4096; idx += 256) {
            int row = idx >> 8;
            sbuf[idx] = (n0 + row < NN) ? x[n0 * W_ + idx] : 0.f;
        }
        __syncthreads();
        unsigned* out = (unsigned*)(g_xf + (size_t)b * 512);
        for (int idx = tid; idx < 2048; idx += 256) {
            int i = idx & 3;
            int t = (idx >> 2) & 31;
            int kt = idx >> 7;
            int er = (t >> 2) + ((i & 1) << 3);
            int kc = kt * 16 + (t & 3) * 2 + ((i >> 1) << 3);
            out[idx] = packh(sbuf[er * W_ + kc], sbuf[er * W_ + kc + 1]);
        }
        return;
    }
    b -= 628;
    if (b < 64) {
        // W_pre -> B-frags natural (g_wfpre), 16384 uint2 total
        int idx = b * 256 + tid;
        int nt = idx >> 9;          // 0..31
        int kt = (idx >> 5) & 15;
        int lane = idx & 31;
        int tg = lane & 3, gid = lane >> 2;
        int col = nt * 8 + gid;
        int k0 = kt * 16 + tg * 2;
        uint2 o;
        o.x = packh(Wpre[k0 * W_ + col], Wpre[(k0 + 1) * W_ + col]);
        o.y = packh(Wpre[(k0 + 8) * W_ + col], Wpre[(k0 + 9) * W_ + col]);
        g_wfpre[(nt * 16 + kt) * 32 + lane] = o;
        return;
    }
    b -= 64;
    if (b < 192) {
        int idx = b * 256 + tid;        // 0..49151
        int m = idx / 16384;
        int j = idx & 16383;
        int nt = j >> 8;
        int kt = (j >> 5) & 7;
        int lane = j & 31;
        int tg = lane & 3, gid = lane >> 2;
        const float* W = (m == 0) ? W0 : ((m == 1) ? W1 : W2);
        float sc = __expf((m == 2) ? init0[3] : init0[2]);
        int col = permcol(nt, gid);
        int k0 = kt * 16 + tg * 2;
        uint2 o;
        o.x = packh(W[k0 * H_ + col] * sc, W[(k0 + 1) * H_ + col] * sc);
        o.y = packh(W[(k0 + 8) * H_ + col] * sc, W[(k0 + 9) * H_ + col] * sc);
        int chunk = nt >> 3, nt8 = nt & 7;
        g_wf2h[((chunk * 3 + m) * 8 + nt8) * 256 + kt * 32 + lane] = o;
        return;
    }
    b -= 192;
    if (b < 512) {
        int idx = b * 256 + tid;  // 0..131071
        int m = idx >> 15;
        int j = idx & 32767;
        int nt = j >> 9;
        int kt = (j >> 5) & 15;
        int lane = j & 31;
        int tg = lane & 3, gid = lane >> 2;
        const float* W = (m == 0) ? Wq : ((m == 1) ? Wk : ((m == 2) ? Wv : Wm));
        int col = permcol(nt, gid);
        int k0 = kt * 16 + tg * 2;
        uint2 o;
        o.x = packh(W[k0 * H_ + col], W[(k0 + 1) * H_ + col]);
        o.y = packh(W[(k0 + 8) * H_ + col], W[(k0 + 9) * H_ + col]);
        int s = m * 8 + (nt >> 3);
        g_wfnh[((s * 8 + (nt & 7)) * 16 + kt) * 32 + lane] = o;
        return;
    }
    b -= 512;
    if (b < 128) {
        int idx = b * 256 + tid;  // 0..32767
        int nt = idx >> 10;
        int kt = (idx >> 5) & 31;
        int lane = idx & 31;
        int tg = lane & 3, gid = lane >> 2;
        int col = permcol(nt, gid);
        int k0 = kt * 16 + tg * 2;
        uint2 o;
        o.x = packh(Wpost[k0 * W_ + col], Wpost[(k0 + 1) * W_ + col]);
        o.y = packh(Wpost[(k0 + 8) * W_ + col], Wpost[(k0 + 9) * W_ + col]);
        int stage = nt >> 3;
        g_wfph[((stage * 8 + (nt & 7)) * 32 + kt) * 32 + lane] = o;
        return;
    }
    b -= 128;
    // ---- ee embedding mix -> A-frags ----
    float* ee_s = sbuf;
    int e0 = b * 32;
    if (tid < 128) s_attr[tid] = edge_attr[e0 * 4 + tid];
    float ew0 = __expf(init0_e[0]), ew1 = __expf(init0_e[1]);
    float ew2 = __expf(init0_e[2]), ew3 = __expf(init0_e[3]);
    float rs = rsqrtf(ew0 + ew1 + ew2 + ew3);
    ew0 *= rs; ew1 *= rs; ew2 *= rs; ew3 *= rs;
    __syncthreads();
    for (int idx = tid; idx < 32 * EW_; idx += 256) {
        int e = idx >> 7;
        int c = idx & (EW_ - 1);
        int a0 = s_attr[e * 4 + 0], a1 = s_attr[e * 4 + 1];
        int a2 = s_attr[e * 4 + 2], a3 = s_attr[e * 4 + 3];
        float v = emb0[a0 * EW_ + c] * ew0 + emb1[a1 * EW_ + c] * ew1 +
                  emb2[a2 * EW_ + c] * ew2 + emb3[a3 * EW_ + c] * ew3;
        ee_s[idx] = 0.5f * (v + edge_embed[(e0 + e) * EW_ + c]);
    }
    __syncthreads();
    unsigned* out = (unsigned*)(g_eefh + (size_t)b * 512);
    for (int idx = tid; idx < 2048; idx += 256) {
        int i = idx & 3;
        int t = (idx >> 2) & 31;
        int kt = (idx >> 7) & 7;
        int let = idx >> 10;
        int er = (t >> 2) + ((i & 1) << 3);
        int kc = kt * 16 + (t & 3) * 2 + ((i >> 1) << 3);
        out[idx] = packh(ee_s[(let * 16 + er) * EW_ + kc],
                         ee_s[(let * 16 + er) * EW_ + kc + 1]);
    }
}

// ---------------------------------------------------------------------------
// Tensorized pre: xx = LN(x@W_pre + b_pre), 64 nodes/block, fp16 mma.
// ---------------------------------------------------------------------------
__global__ void __launch_bounds__(256, 1) k_preT(const float* __restrict__ bpre) {
    extern __shared__ char dsm[];
    uint4* a_sm = (uint4*)dsm;               // 32KB
    uint2* b_sm = (uint2*)(dsm + 32768);     // 128KB (aliased by ys after mma)
    float* ys = (float*)(dsm + 32768);       // [64][256] = 64KB
    __shared__ float s_mean[64], s_rstd[64];
    __shared__ __align__(8) unsigned long long mbar_s[2];

    int tid = threadIdx.x;
    int lane = tid & 31, wid = tid >> 5;
    int mg = wid >> 2;
    int ng = wid & 3;
    int gid = lane >> 2, tg = lane & 3;
    int blk = blockIdx.x;

    unsigned mbA = s2u(&mbar_s[0]);
    unsigned mbB = s2u(&mbar_s[1]);
    if (tid == 0) {
        mbar_init(mbA, 1);
        mbar_init(mbB, 1);
    }
    __syncthreads();
    if (tid == 0) {
        mbar_expect(mbA, 32768);
        bulk_g2s(s2u(a_sm), g_xf + (size_t)blk * 2048, 32768, mbA);
        mbar_expect(mbB, 131072);
        bulk_g2s(s2u(b_sm), g_wfpre, 65536, mbB);
        bulk_g2s(s2u(b_sm + 8192), g_wfpre + 8192, 65536, mbB);
    }

    float acc[2][8][4];
#pragma unroll
    for (int mt = 0; mt < 2; mt++)
#pragma unroll
        for (int nt = 0; nt < 8; nt++)
#pragma unroll
            for (int c = 0; c < 4; c++) acc[mt][nt][c] = 0.f;

    const uint4* aw = a_sm + mg * 1024 + lane;
    const uint2* bw = b_sm + ng * 8 * 512 + lane;

    mbar_wait(mbA, 0);
    mbar_wait(mbB, 0);

#pragma unroll 4
    for (int kt = 0; kt < 16; kt++) {
        uint4 av0 = aw[kt * 32];
        uint4 av1 = aw[512 + kt * 32];
#pragma unroll
        for (int nt = 0; nt < 8; nt++) {
            uint2 bv = bw[nt * 512 + kt * 32];
            mma16(acc[0][nt], av0, bv);
            mma16(acc[1][nt], av1, bv);
        }
    }
    __syncthreads();  // done reading b_sm; safe to alias ys

#pragma unroll
    for (int mt = 0; mt < 2; mt++) {
        int r0 = (mg * 2 + mt) * 16 + gid;
        int r1 = r0 + 8;
#pragma unroll
        for (int nt = 0; nt < 8; nt++) {
            int c = ng * 64 + nt * 8 + tg * 2;
            float2 bb = *(const float2*)(bpre + c);
            ys[r0 * W_ + c] = acc[mt][nt][0] + bb.x;
            ys[r0 * W_ + c + 1] = acc[mt][nt][1] + bb.y;
            ys[r1 * W_ + c] = acc[mt][nt][2] + bb.x;
            ys[r1 * W_ + c + 1] = acc[mt][nt][3] + bb.y;
        }
    }
    __syncthreads();

#pragma unroll
    for (int rr = 0; rr < 8; rr++) {
        int row = wid * 8 + rr;
        float s = 0.f;
#pragma unroll
        for (int m = 0; m < W_ / 32; m++) s += ys[row * W_ + lane + 32 * m];
#pragma unroll
        for (int off = 16; off > 0; off >>= 1) s += __shfl_xor_sync(0xffffffffu, s, off);
        float mean = s * (1.0f / W_);
        float v = 0.f;
#pragma unroll
        for (int m = 0; m < W_ / 32; m++) {
            float d = ys[row * W_ + lane + 32 * m] - mean;
            v += d * d;
        }
#pragma unroll
        for (int off = 16; off > 0; off >>= 1) v += __shfl_xor_sync(0xffffffffu, v, off);
        if (lane == 0) {
            s_mean[row] = mean;
            s_rstd[row] = rsqrtf(v * (1.0f / W_) + 1e-5f);
        }
    }
    __syncthreads();

    unsigned* out = (unsigned*)(g_xxfh + (size_t)blk * 2048);
    for (int idx = tid; idx < 8192; idx += 256) {
        int w = idx & 2047;
        int tile = idx >> 11;
        int i = w & 3;
        int t = (w >> 2) & 31;
        int kt = w >> 7;
        int er = (t >> 2) + ((i & 1) << 3);
        int row = tile * 16 + er;
        int kc = kt * 16 + (t & 3) * 2 + ((i >> 1) << 3);
        float mean = s_mean[row], rstd = s_rstd[row];
        out[idx] = packh((ys[row * W_ + kc] - mean) * rstd,
                         (ys[row * W_ + kc + 1] - mean) * rstd);
    }
}

// ---------------------------------------------------------------------------
// fp16 node projections: 64 nodes/block, 32 passes, float4 epilogue stores.
// ---------------------------------------------------------------------------
__global__ void __launch_bounds__(256, 2) k_projz(const float* __restrict__ bq,
                                                  const float* __restrict__ bk,
                                                  const float* __restrict__ bv,
                                                  const float* __restrict__ bm,
                                                  const float* __restrict__ br0,
                                                  const float* __restrict__ br1,
                                                  const float* __restrict__ br2,
                                                  const float* __restrict__ init0) {
    extern __shared__ char dsm[];
    uint4* a_sm = (uint4*)dsm;               // 32KB
    uint2* b_sm = (uint2*)(dsm + 32768);     // 2 x 32KB
    __shared__ __align__(8) unsigned long long mbar_s[3];

    int tid = threadIdx.x;
    int lane = tid & 31, wid = tid >> 5;
    int mg = wid >> 2;
    int ng = wid & 3;
    int gid = lane >> 2, tg = lane & 3;
    int blk = blockIdx.x;

    unsigned mbA = s2u(&mbar_s[0]);
    unsigned mb0 = s2u(&mbar_s[1]);
    unsigned mb1 = s2u(&mbar_s[2]);
    if (tid == 0) {
        mbar_init(mbA, 1);
        mbar_init(mb0, 1);
        mbar_init(mb1, 1);
    }
    float s_e = __expf(init0[2]);
    float s_v = __expf(init0[3]);
    __syncthreads();

    if (tid == 0) {
        mbar_expect(mbA, 32768);
        bulk_g2s(s2u(a_sm), g_xxfh + (size_t)blk * 2048, 32768, mbA);
        mbar_expect(mb0, 32768);
        bulk_g2s(s2u(b_sm), g_wfnh, 32768, mb0);
        mbar_expect(mb1, 32768);
        bulk_g2s(s2u(b_sm + 4096), g_wfnh + 4096, 32768, mb1);
    }

    {
        int r0 = blk * 64;
        float4 z = make_float4(0.f, 0.f, 0.f, 0.f);
        for (int i = tid; i < 64 * (H_ / 4); i += 256) {
            int r = r0 + (i >> 7);
            if (r < NN) *(float4*)(g_agg + (size_t)r * H_ + ((i & 127) << 2)) = z;
        }
    }

    const uint4* aw = a_sm + mg * 1024 + lane;
    const uint2* bw = b_sm + (ng * 2) * 512 + lane;

    mbar_wait(mbA, 0);
    int ph0 = 0, ph1 = 0;

#pragma unroll 1
    for (int s = 0; s < 32; s++) {
        int buf = s & 1;
        if (buf == 0) { mbar_wait(mb0, ph0); ph0 ^= 1; }
        else          { mbar_wait(mb1, ph1); ph1 ^= 1; }

        float acc[2][2][4];
#pragma unroll
        for (int mt = 0; mt < 2; mt++)
#pragma unroll
            for (int nt = 0; nt < 2; nt++)
#pragma unroll
                for (int c = 0; c < 4; c++) acc[mt][nt][c] = 0.f;

#pragma unroll 4
        for (int kt = 0; kt < 16; kt++) {
            uint4 av0 = aw[kt * 32];
            uint4 av1 = aw[512 + kt * 32];
            uint2 bv0 = bw[buf * 4096 + kt * 32];
            uint2 bv1 = bw[buf * 4096 + 512 + kt * 32];
            mma16(acc[0][0], av0, bv0);
            mma16(acc[0][1], av0, bv1);
            mma16(acc[1][0], av1, bv0);
            mma16(acc[1][1], av1, bv1);
        }
        __syncthreads();
        if (tid == 0 && s + 2 < 32) {
            if (buf == 0) { mbar_expect(mb0, 32768); bulk_g2s(s2u(b_sm), g_wfnh + (size_t)(s + 2) * 4096, 32768, mb0); }
            else          { mbar_expect(mb1, 32768); bulk_g2s(s2u(b_sm + 4096), g_wfnh + (size_t)(s + 2) * 4096, 32768, mb1); }
        }

        int m = s >> 3, cc = s & 7;
        const float* bmain = (m == 0) ? bq : ((m == 1) ? bk : ((m == 2) ? bv : bm));
        const float* badd  = (m == 0) ? br0 : ((m == 1) ? br1 : br2);
        float scale = (m < 2) ? s_e : s_v;
        float* dst = (m == 0) ? g_qn : ((m == 1) ? g_kn : ((m == 2) ? g_vn : g_m0));
        int col = cc * 64 + ng * 16 + tg * 4;
        float4 bb = *(const float4*)(bmain + col);
        if (m < 3) {
            float4 b2 = *(const float4*)(badd + col);
            bb = make_float4(bb.x + b2.x * scale, bb.y + b2.y * scale,
                             bb.z + b2.z * scale, bb.w + b2.w * scale);
        }
#pragma unroll
        for (int mt = 0; mt < 2; mt++) {
            int r0 = blk * 64 + mg * 32 + mt * 16 + gid;
            int r1 = r0 + 8;
            float4 o0 = make_float4(acc[mt][0][0] + bb.x, acc[mt][0][1] + bb.y,
                                    acc[mt][1][0] + bb.z, acc[mt][1][1] + bb.w);
            float4 o1 = make_float4(acc[mt][0][2] + bb.x, acc[mt][0][3] + bb.y,
                                    acc[mt][1][2] + bb.z, acc[mt][1][3] + bb.w);
            if (m == 3) {
                o0 = make_float4(gelu_fast(o0.x), gelu_fast(o0.y), gelu_fast(o0.z), gelu_fast(o0.w));
                o1 = make_float4(gelu_fast(o1.x), gelu_fast(o1.y), gelu_fast(o1.z), gelu_fast(o1.w));
            }
            if (r0 < NN) *(float4*)(dst + (size_t)r0 * H_ + col) = o0;
            if (r1 < NN) *(float4*)(dst + (size_t)r1 * H_ + col) = o1;
        }
    }
}

// ---------------------------------------------------------------------------
// fp16 edge kernel: 128 edges/block, 512 threads (4 mg x 4 ng).
// One __syncthreads per chunk (p_buf double-buffered over chunks).
// Epilogue uses fast erf-gelu + __expf. (Best-measured R11 schedule.)
// ---------------------------------------------------------------------------
__global__ void __launch_bounds__(512) k_edge(const int* __restrict__ edge_index,
                                              const float* __restrict__ init0) {
    extern __shared__ char dsm[];
    uint4* a_sm = (uint4*)dsm;               // 32KB
    uint2* b_sm = (uint2*)(dsm + 32768);     // 2 x 48KB
    __shared__ int s_src[128], s_dst[128];
    __shared__ float p_buf[2][4][128];
    __shared__ __align__(8) unsigned long long mbar_s[3];

    int tid = threadIdx.x;
    int lane = tid & 31, wid = tid >> 5;
    int mg = wid >> 2;
    int ng = wid & 3;
    int gid = lane >> 2, tg = lane & 3;
    int e0 = blockIdx.x * 128;

    unsigned mbA = s2u(&mbar_s[0]);
    unsigned mb0 = s2u(&mbar_s[1]);
    unsigned mb1 = s2u(&mbar_s[2]);

    if (tid < 128) {
        s_src[tid] = edge_index[e0 + tid];
        s_dst[tid] = edge_index[NE + e0 + tid];
    }
    if (tid == 0) {
        mbar_init(mbA, 1);
        mbar_init(mb0, 1);
        mbar_init(mb1, 1);
    }
    float c0 = init0[0] * 0.125f;
    float c1 = init0[1];
    __syncthreads();

    if (tid == 0) {
        mbar_expect(mbA, 32768);
        bulk_g2s(s2u(a_sm), g_eefh + (size_t)blockIdx.x * 2048, 32768, mbA);
        mbar_expect(mb0, 49152);
        bulk_g2s(s2u(b_sm), g_wf2h, 49152, mb0);
        mbar_expect(mb1, 49152);
        bulk_g2s(s2u(b_sm + 6144), g_wf2h + 6144, 49152, mb1);
    }

    int rd0[2], rd1[2], rs0[2], rs1[2];
#pragma unroll
    for (int mt = 0; mt < 2; mt++) {
        int el = mg * 32 + mt * 16 + gid;
        rd0[mt] = s_dst[el];
        rd1[mt] = s_dst[el + 8];
        rs0[mt] = s_src[el];
        rs1[mt] = s_src[el + 8];
    }

    const uint4* aw = a_sm + mg * 512 + lane;
    const uint2* bw = b_sm + (ng * 2) * 256 + lane;

    mbar_wait(mbA, 0);
    int ph0 = 0, ph1 = 0;

#pragma unroll 1
    for (int chunk = 0; chunk < 8; chunk++) {
        float acc[3][2][2][4];
#pragma unroll
        for (int m = 0; m < 3; m++)
#pragma unroll
            for (int mt = 0; mt < 2; mt++)
#pragma unroll
                for (int nt = 0; nt < 2; nt++)
#pragma unroll
                    for (int c = 0; c < 4; c++) acc[m][mt][nt][c] = 0.f;

        int colbase = chunk * 64 + ng * 16 + tg * 4;
        int bufbase = (chunk & 1) * 6144;
        int pb = chunk & 1;

        // prefetch q/k gathers
        float4 qv[2][2], kv[2][2];
#pragma unroll
        for (int mt = 0; mt < 2; mt++) {
            qv[mt][0] = *(const float4*)(g_qn + (size_t)rd0[mt] * H_ + colbase);
            qv[mt][1] = *(const float4*)(g_qn + (size_t)rd1[mt] * H_ + colbase);
            kv[mt][0] = *(const float4*)(g_kn + (size_t)rs0[mt] * H_ + colbase);
            kv[mt][1] = *(const float4*)(g_kn + (size_t)rs1[mt] * H_ + colbase);
        }

        if ((chunk & 1) == 0) { mbar_wait(mb0, ph0); ph0 ^= 1; }
        else                  { mbar_wait(mb1, ph1); ph1 ^= 1; }

#pragma unroll
        for (int kt = 0; kt < 4; kt++) {
            uint4 av0 = aw[kt * 32];
            uint4 av1 = aw[256 + kt * 32];
            uint2 bv[3][2];
#pragma unroll
            for (int m = 0; m < 3; m++)
#pragma unroll
                for (int nt = 0; nt < 2; nt++)
                    bv[m][nt] = bw[bufbase + (m * 8 + nt) * 256 + kt * 32];
#pragma unroll
            for (int m = 0; m < 3; m++)
#pragma unroll
                for (int nt = 0; nt < 2; nt++) {
                    mma16(acc[m][0][nt], av0, bv[m][nt]);
                    mma16(acc[m][1][nt], av1, bv[m][nt]);
                }
        }

        // prefetch v gathers (hide under second mma half)
        float4 vv[2][2];
#pragma unroll
        for (int mt = 0; mt < 2; mt++) {
            vv[mt][0] = *(const float4*)(g_vn + (size_t)rs0[mt] * H_ + colbase);
            vv[mt][1] = *(const float4*)(g_vn + (size_t)rs1[mt] * H_ + colbase);
        }

#pragma unroll
        for (int kt = 4; kt < 8; kt++) {
            uint4 av0 = aw[kt * 32];
            uint4 av1 = aw[256 + kt * 32];
            uint2 bv[3][2];
#pragma unroll
            for (int m = 0; m < 3; m++)
#pragma unroll
                for (int nt = 0; nt < 2; nt++)
                    bv[m][nt] = bw[bufbase + (m * 8 + nt) * 256 + kt * 32];
#pragma unroll
            for (int m = 0; m < 3; m++)
#pragma unroll
                for (int nt = 0; nt < 2; nt++) {
                    mma16(acc[m][0][nt], av0, bv[m][nt]);
                    mma16(acc[m][1][nt], av1, bv[m][nt]);
                }
        }

        float p[2][2];
#pragma unroll
        for (int mt = 0; mt < 2; mt++) {
            p[mt][0] = (qv[mt][0].x + acc[0][mt][0][0]) * (kv[mt][0].x + acc[1][mt][0][0])
                     + (qv[mt][0].y + acc[0][mt][0][1]) * (kv[mt][0].y + acc[1][mt][0][1])
                     + (qv[mt][0].z + acc[0][mt][1][0]) * (kv[mt][0].z + acc[1][mt][1][0])
                     + (qv[mt][0].w + acc[0][mt][1][1]) * (kv[mt][0].w + acc[1][mt][1][1]);
            p[mt][1] = (qv[mt][1].x + acc[0][mt][0][2]) * (kv[mt][1].x + acc[1][mt][0][2])
                     + (qv[mt][1].y + acc[0][mt][0][3]) * (kv[mt][1].y + acc[1][mt][0][3])
                     + (qv[mt][1].z + acc[0][mt][1][2]) * (kv[mt][1].z + acc[1][mt][1][2])
                     + (qv[mt][1].w + acc[0][mt][1][3]) * (kv[mt][1].w + acc[1][mt][1][3]);
        }
#pragma unroll
        for (int off = 1; off <= 2; off <<= 1) {
            p[0][0] += __shfl_xor_sync(0xffffffffu, p[0][0], off);
            p[0][1] += __shfl_xor_sync(0xffffffffu, p[0][1], off);
            p[1][0] += __shfl_xor_sync(0xffffffffu, p[1][0], off);
            p[1][1] += __shfl_xor_sync(0xffffffffu, p[1][1], off);
        }
        if (tg == 0) {
#pragma unroll
            for (int mt = 0; mt < 2; mt++) {
                int el = mg * 32 + mt * 16 + gid;
                p_buf[pb][ng][el] = p[mt][0];
                p_buf[pb][ng][el + 8] = p[mt][1];
            }
        }
        __syncthreads();   // pbuf write->read; also all warps done with B buf
        if (tid == 0 && chunk < 6) {
            if ((chunk & 1) == 0) { mbar_expect(mb0, 49152); bulk_g2s(s2u(b_sm), g_wf2h + (size_t)(chunk + 2) * 6144, 49152, mb0); }
            else                  { mbar_expect(mb1, 49152); bulk_g2s(s2u(b_sm + 6144), g_wf2h + (size_t)(chunk + 2) * 6144, 49152, mb1); }
        }

#pragma unroll
        for (int mt = 0; mt < 2; mt++) {
            int el = mg * 32 + mt * 16 + gid;
            float sum0 = p_buf[pb][0][el] + p_buf[pb][1][el] + p_buf[pb][2][el] + p_buf[pb][3][el];
            float sum1 = p_buf[pb][0][el + 8] + p_buf[pb][1][el + 8] + p_buf[pb][2][el + 8] + p_buf[pb][3][el + 8];
            float att0 = __expf(sum0 * c0 + c1);
            float att1 = __expf(sum1 * c0 + c1);
            red4(g_agg + (size_t)rd0[mt] * H_ + colbase,
                 gelu_fast(vv[mt][0].x + acc[2][mt][0][0]) * att0,
                 gelu_fast(vv[mt][0].y + acc[2][mt][0][1]) * att0,
                 gelu_fast(vv[mt][0].z + acc[2][mt][1][0]) * att0,
                 gelu_fast(vv[mt][0].w + acc[2][mt][1][1]) * att0);
            red4(g_agg + (size_t)rd1[mt] * H_ + colbase,
                 gelu_fast(vv[mt][1].x + acc[2][mt][0][2]) * att1,
                 gelu_fast(vv[mt][1].y + acc[2][mt][0][3]) * att1,
                 gelu_fast(vv[mt][1].z + acc[2][mt][1][2]) * att1,
                 gelu_fast(vv[mt][1].w + acc[2][mt][1][3]) * att1);
        }
    }
}

// ---------------------------------------------------------------------------
// fp16 post kernel: out = x + (m0+agg) @ W_post + b_post. float4 A-build.
// ---------------------------------------------------------------------------
__global__ void __launch_bounds__(256) k_post(const float* __restrict__ x,
                                              const float* __restrict__ bp,
                                              float* __restrict__ out) {
    extern __shared__ char dsm[];
    uint4* a_sm = (uint4*)dsm;               // 64KB
    uint2* b_sm = (uint2*)(dsm + 65536);     // 2 x 64KB
    __shared__ __align__(8) unsigned long long mbar_s[2];

    int tid = threadIdx.x;
    int lane = tid & 31, wid = tid >> 5;
    int mg = wid >> 2;
    int ng = wid & 3;
    int gid = lane >> 2, tg = lane & 3;
    int blk = blockIdx.x;

    unsigned mb0 = s2u(&mbar_s[0]);
    unsigned mb1 = s2u(&mbar_s[1]);
    if (tid == 0) {
        mbar_init(mb0, 1);
        mbar_init(mb1, 1);
    }
    __syncthreads();
    if (tid == 0) {
        mbar_expect(mb0, 65536);
        bulk_g2s(s2u(b_sm), g_wfph, 65536, mb0);
        mbar_expect(mb1, 65536);
        bulk_g2s(s2u(b_sm + 8192), g_wfph + 8192, 65536, mb1);
    }

    {
        unsigned* aword = (unsigned*)a_sm;
        for (int idx = tid; idx < 8192; idx += 256) {
            int rl = idx >> 7;
            int c4 = (idx & 127) << 2;
            int row = blk * 64 + rl;
            float4 f = make_float4(0.f, 0.f, 0.f, 0.f);
            if (row < NN) {
                float4 m4 = *(const float4*)(g_m0 + (size_t)row * H_ + c4);
                float4 a4 = *(const float4*)(g_agg + (size_t)row * H_ + c4);
                f = make_float4(m4.x + a4.x, m4.y + a4.y, m4.z + a4.z, m4.w + a4.w);
            }
            int mt = rl >> 4;
            int er = rl & 15;
            int kt = c4 >> 4;
            int i = (er >> 3) | (((c4 >> 3) & 1) << 1);
            int tb = (er & 7) * 4 + ((c4 >> 1) & 3);
            int base = ((mt * 32 + kt) * 32 + tb) * 4 + i;
            aword[base] = packh(f.x, f.y);
            aword[base + 4] = packh(f.z, f.w);
        }
    }
    __syncthreads();

    const uint4* aw = a_sm + mg * 2048 + lane;
    const uint2* bw = b_sm + (ng * 2) * 1024 + lane;
    int ph0 = 0, ph1 = 0;

#pragma unroll 1
    for (int s = 0; s < 4; s++) {
        int buf = s & 1;
        if (buf == 0) { mbar_wait(mb0, ph0); ph0 ^= 1; }
        else          { mbar_wait(mb1, ph1); ph1 ^= 1; }

        float acc[2][2][4];
#pragma unroll
        for (int mt = 0; mt < 2; mt++)
#pragma unroll
            for (int nt = 0; nt < 2; nt++)
#pragma unroll
                for (int c = 0; c < 4; c++) acc[mt][nt][c] = 0.f;

#pragma unroll 4
        for (int kt = 0; kt < 32; kt++) {
            uint4 av0 = aw[kt * 32];
            uint4 av1 = aw[1024 + kt * 32];
            uint2 bv0 = bw[buf * 8192 + kt * 32];
            uint2 bv1 = bw[buf * 8192 + 1024 + kt * 32];
            mma16(acc[0][0], av0, bv0);
            mma16(acc[0][1], av0, bv1);
            mma16(acc[1][0], av1, bv0);
            mma16(acc[1][1], av1, bv1);
        }
        __syncthreads();
        if (tid == 0 && s + 2 < 4) {
            if (buf == 0) { mbar_expect(mb0, 65536); bulk_g2s(s2u(b_sm), g_wfph + (size_t)(s + 2) * 8192, 65536, mb0); }
            else          { mbar_expect(mb1, 65536); bulk_g2s(s2u(b_sm + 8192), g_wfph + (size_t)(s + 2) * 8192, 65536, mb1); }
        }

        int col = s * 64 + ng * 16 + tg * 4;
        float4 bb = *(const float4*)(bp + col);
#pragma unroll
        for (int mt = 0; mt < 2; mt++) {
            int r0 = blk * 64 + mg * 32 + mt * 16 + gid;
            int r1 = r0 + 8;
            if (r0 < NN) {
                float4 xx0 = *(const float4*)(x + (size_t)r0 * W_ + col);
                *(float4*)(out + (size_t)r0 * W_ + col) =
                    make_float4(xx0.x + acc[mt][0][0] + bb.x, xx0.y + acc[mt][0][1] + bb.y,
                                xx0.z + acc[mt][1][0] + bb.z, xx0.w + acc[mt][1][1] + bb.w);
            }
            if (r1 < NN) {
                float4 xx1 = *(const float4*)(x + (size_t)r1 * W_ + col);
                *(float4*)(out + (size_t)r1 * W_ + col) =
                    make_float4(xx1.x + acc[mt][0][2] + bb.x, xx1.y + acc[mt][0][3] + bb.y,
                                xx1.z + acc[mt][1][2] + bb.z, xx1.w + acc[mt][1][3] + bb.w);
            }
        }
    }
}

extern "C" void kernel_launch(void* const* d_in, const int* in_sizes, int n_in,
                              void* d_out, int out_size) {
    const float* x          = (const float*)d_in[0];
    const int*   edge_index = (const int*)d_in[1];
    const int*   edge_attr  = (const int*)d_in[2];
    const float* edge_embed = (const float*)d_in[3];
    const float* emb0       = (const float*)d_in[4];
    const float* emb1       = (const float*)d_in[5];
    const float* emb2       = (const float*)d_in[6];
    const float* emb3       = (const float*)d_in[7];
    const float* init0_e    = (const float*)d_in[8];
    const float* init0      = (const float*)d_in[9];
    const float* W_pre      = (const float*)d_in[10];
    const float* b_pre      = (const float*)d_in[11];
    const float* W_msg0     = (const float*)d_in[12];
    const float* b_msg0     = (const float*)d_in[13];
    const float* W_q        = (const float*)d_in[14];
    const float* b_q        = (const float*)d_in[15];
    const float* W_k        = (const float*)d_in[16];
    const float* b_k        = (const float*)d_in[17];
    const float* W_v        = (const float*)d_in[18];
    const float* b_v        = (const float*)d_in[19];
    const float* W_r0       = (const float*)d_in[20];
    const float* b_r0       = (const float*)d_in[21];
    const float* W_r1       = (const float*)d_in[22];
    const float* b_r1       = (const float*)d_in[23];
    const float* W_r2       = (const float*)d_in[24];
    const float* b_r2       = (const float*)d_in[25];
    const float* W_post     = (const float*)d_in[26];
    const float* b_post     = (const float*)d_in[27];
    float* out = (float*)d_out;

    cudaFuncSetAttribute(k_edge, cudaFuncAttributeMaxDynamicSharedMemorySize, 131072);
    cudaFuncSetAttribute(k_projz, cudaFuncAttributeMaxDynamicSharedMemorySize, 98304);
    cudaFuncSetAttribute(k_post, cudaFuncAttributeMaxDynamicSharedMemorySize, 196608);
    cudaFuncSetAttribute(k_preT, cudaFuncAttributeMaxDynamicSharedMemorySize, 163840);

    k_wfeef<<<1524 + NE / 32, 256>>>(x, W_pre,
                                     W_r0, W_r1, W_r2, W_q, W_k, W_v, W_msg0, W_post,
                                     edge_attr, edge_embed,
                                     emb0, emb1, emb2, emb3, init0_e, init0);
    k_preT<<<NP / 64, 256, 163840>>>(b_pre);
    k_projz<<<NP / 64, 256, 98304>>>(b_q, b_k, b_v, b_msg0, b_r0, b_r1, b_r2, init0);
    k_edge<<<NE / 128, 512, 131072>>>(edge_index, init0);
    k_post<<<NP / 64, 256, 196608>>>(x, b_post, out);
}

// round 15
// speedup vs baseline: 1.1255x; 1.0258x over previous
#include <cuda_runtime.h>
#include <cuda_fp16.h>
#include <math.h>

#define NN 10000
#define NP 10048   // padded nodes (157 * 64)
#define NE 160000
#define W_ 256
#define H_ 512
#define EW_ 128

// Scratch (static device memory — no allocation allowed)
__device__ __half g_qnh[NN * H_];  // fp16 node caches (half2-packed pairs)
__device__ __half g_knh[NN * H_];
__device__ __half g_vnh[NN * H_];
__device__ float g_m0[NN * H_];
__device__ float g_agg[NN * H_];
__device__ uint4 g_eefh[NE * 16];              // ee fp16 A-frags
__device__ uint2 g_wf2h[8 * 3 * 8 * 8 * 32];   // Wr0..2 fp16 B-frags (perm cols, scales folded)
__device__ uint2 g_wfnh[4 * 64 * 16 * 32];     // Wq/Wk/Wv/Wm fp16 B-frags (perm cols)
__device__ uint2 g_wfph[32 * 32 * 32];         // W_post fp16 B-frags (perm cols)
__device__ uint4 g_xxfh[(NP / 16) * 512];      // LN(pre(x)) fp16 A-frags
__device__ uint4 g_xf[(NP / 16) * 512];        // raw x fp16 A-frags
__device__ uint2 g_wfpre[32 * 16 * 32];        // W_pre fp16 B-frags (natural cols, 128KB)

// Fast branch-free erf-gelu (Abramowitz-Stegun 7.1.25, |err| <= 2.5e-5 abs)
__device__ __forceinline__ float gelu_fast(float h) {
    float s = h * 0.70710678118654752f;
    float a = fabsf(s);
    float t = __fdividef(1.0f, fmaf(0.47047f, a, 1.0f));
    float p = t * fmaf(t, fmaf(t, 0.7478556f, -0.0958798f), 0.3480242f);
    float e = __expf(-s * s);
    float erfa = fmaf(-p, e, 1.0f);
    float er = copysignf(erfa, s);
    return 0.5f * h * (1.0f + er);
}

__device__ __forceinline__ unsigned packh(float a, float b) {
    __half2 h = __floats2half2_rn(a, b);
    return *(unsigned*)&h;
}

// load 4 consecutive half cols as float4 (8B LDG.64)
__device__ __forceinline__ float4 ldh4(const __half* p) {
    uint2 u = *(const uint2*)p;
    float2 a = __half22float2(*(__half2*)&u.x);
    float2 b = __half22float2(*(__half2*)&u.y);
    return make_float4(a.x, a.y, b.x, b.y);
}

__device__ __forceinline__ void mma16(float* d, const uint4& a, const uint2& b) {
    asm volatile(
        "mma.sync.aligned.m16n8k16.row.col.f32.f16.f16.f32 "
        "{%0,%1,%2,%3},{%4,%5,%6,%7},{%8,%9},{%0,%1,%2,%3};"
        : "+f"(d[0]), "+f"(d[1]), "+f"(d[2]), "+f"(d[3])
        : "r"(a.x), "r"(a.y), "r"(a.z), "r"(a.w), "r"(b.x), "r"(b.y));
}

__device__ __forceinline__ void red4(float* p, float a, float b, float c, float d) {
    asm volatile("red.global.add.v4.f32 [%0], {%1,%2,%3,%4};"
                 :: "l"(p), "f"(a), "f"(b), "f"(c), "f"(d) : "memory");
}

// ---- mbarrier + bulk-copy helpers ----
__device__ __forceinline__ unsigned s2u(const void* p) {
    return (unsigned)__cvta_generic_to_shared(p);
}
__device__ __forceinline__ void mbar_init(unsigned mbar, unsigned cnt) {
    asm volatile("mbarrier.init.shared.b64 [%0], %1;" :: "r"(mbar), "r"(cnt) : "memory");
}
__device__ __forceinline__ void mbar_expect(unsigned mbar, unsigned bytes) {
    asm volatile("mbarrier.arrive.expect_tx.shared.b64 _, [%0], %1;"
                 :: "r"(mbar), "r"(bytes) : "memory");
}
__device__ __forceinline__ void bulk_g2s(unsigned dst, const void* src, unsigned bytes,
                                         unsigned mbar) {
    asm volatile("cp.async.bulk.shared::cta.global.mbarrier::complete_tx::bytes "
                 "[%0], [%1], %2, [%3];"
                 :: "r"(dst), "l"(src), "r"(bytes), "r"(mbar) : "memory");
}
__device__ __forceinline__ void mbar_wait(unsigned mbar, int phase) {
    asm volatile(
        "{\n\t.reg .pred P;\n\t"
        "W_%=:\n\t"
        "mbarrier.try_wait.parity.acquire.cta.shared::cta.b64 P, [%0], %1, 0x989680;\n\t"
        "@P bra.uni D_%=;\n\t"
        "bra.uni W_%=;\n\t"
        "D_%=:\n\t}"
        :: "r"(mbar), "r"(phase) : "memory");
}

// permuted physical column within a 16-col group
__device__ __forceinline__ int permcol(int nt, int gid) {
    return (nt >> 1) * 16 + (gid >> 1) * 4 + (nt & 1) * 2 + (gid & 1);
}

// ---------------------------------------------------------------------------
// Merged pre-pass (unchanged from champion):
//  [0,628):        x -> fp16 A-frags (g_xf)
//  [628,692):      W_pre -> fp16 B-frags, natural cols (g_wfpre)
//  [692,884):      Wr0..2 -> fp16 B-frags (perm, scales folded)
//  [884,1396):     Wq/Wk/Wv/Wm -> fp16 B-frags (perm)
//  [1396,1524):    W_post -> fp16 B-frags (perm)
//  [1524,6524):    ee embedding mix -> fp16 A-frags
// ---------------------------------------------------------------------------
__global__ void __launch_bounds__(256) k_wfeef(const float* __restrict__ x,
                                               const float* __restrict__ Wpre,
                                               const float* __restrict__ W0,
                                               const float* __restrict__ W1,
                                               const float* __restrict__ W2,
                                               const float* __restrict__ Wq,
                                               const float* __restrict__ Wk,
                                               const float* __restrict__ Wv,
                                               const float* __restrict__ Wm,
                                               const float* __restrict__ Wpost,
                                               const int* __restrict__ edge_attr,
                                               const float* __restrict__ edge_embed,
                                               const float* __restrict__ emb0,
                                               const float* __restrict__ emb1,
                                               const float* __restrict__ emb2,
                                               const float* __restrict__ emb3,
                                               const float* __restrict__ init0_e,
                                               const float* __restrict__ init0) {
    __shared__ float sbuf[4096];   // 16KB
    __shared__ int s_attr[128];
    int tid = threadIdx.x;
    int b = blockIdx.x;

    if (b < 628) {
        int n0 = b * 16;
        for (int idx = tid; idx < 4096; idx += 256) {
            int row = idx >> 8;
            sbuf[idx] = (n0 + row < NN) ? x[n0 * W_ + idx] : 0.f;
        }
        __syncthreads();
        unsigned* out = (unsigned*)(g_xf + (size_t)b * 512);
        for (int idx = tid; idx < 2048; idx += 256) {
            int i = idx & 3;
            int t = (idx >> 2) & 31;
            int kt = idx >> 7;
            int er = (t >> 2) + ((i & 1) << 3);
            int kc = kt * 16 + (t & 3) * 2 + ((i >> 1) << 3);
            out[idx] = packh(sbuf[er * W_ + kc], sbuf[er * W_ + kc + 1]);
        }
        return;
    }
    b -= 628;
    if (b < 64) {
        int idx = b * 256 + tid;
        int nt = idx >> 9;
        int kt = (idx >> 5) & 15;
        int lane = idx & 31;
        int tg = lane & 3, gid = lane >> 2;
        int col = nt * 8 + gid;
        int k0 = kt * 16 + tg * 2;
        uint2 o;
        o.x = packh(Wpre[k0 * W_ + col], Wpre[(k0 + 1) * W_ + col]);
        o.y = packh(Wpre[(k0 + 8) * W_ + col], Wpre[(k0 + 9) * W_ + col]);
        g_wfpre[(nt * 16 + kt) * 32 + lane] = o;
        return;
    }
    b -= 64;
    if (b < 192) {
        int idx = b * 256 + tid;
        int m = idx / 16384;
        int j = idx & 16383;
        int nt = j >> 8;
        int kt = (j >> 5) & 7;
        int lane = j & 31;
        int tg = lane & 3, gid = lane >> 2;
        const float* W = (m == 0) ? W0 : ((m == 1) ? W1 : W2);
        float sc = __expf((m == 2) ? init0[3] : init0[2]);
        int col = permcol(nt, gid);
        int k0 = kt * 16 + tg * 2;
        uint2 o;
        o.x = packh(W[k0 * H_ + col] * sc, W[(k0 + 1) * H_ + col] * sc);
        o.y = packh(W[(k0 + 8) * H_ + col] * sc, W[(k0 + 9) * H_ + col] * sc);
        int chunk = nt >> 3, nt8 = nt & 7;
        g_wf2h[((chunk * 3 + m) * 8 + nt8) * 256 + kt * 32 + lane] = o;
        return;
    }
    b -= 192;
    if (b < 512) {
        int idx = b * 256 + tid;
        int m = idx >> 15;
        int j = idx & 32767;
        int nt = j >> 9;
        int kt = (j >> 5) & 15;
        int lane = j & 31;
        int tg = lane & 3, gid = lane >> 2;
        const float* W = (m == 0) ? Wq : ((m == 1) ? Wk : ((m == 2) ? Wv : Wm));
        int col = permcol(nt, gid);
        int k0 = kt * 16 + tg * 2;
        uint2 o;
        o.x = packh(W[k0 * H_ + col], W[(k0 + 1) * H_ + col]);
        o.y = packh(W[(k0 + 8) * H_ + col], W[(k0 + 9) * H_ + col]);
        int s = m * 8 + (nt >> 3);
        g_wfnh[((s * 8 + (nt & 7)) * 16 + kt) * 32 + lane] = o;
        return;
    }
    b -= 512;
    if (b < 128) {
        int idx = b * 256 + tid;
        int nt = idx >> 10;
        int kt = (idx >> 5) & 31;
        int lane = idx & 31;
        int tg = lane & 3, gid = lane >> 2;
        int col = permcol(nt, gid);
        int k0 = kt * 16 + tg * 2;
        uint2 o;
        o.x = packh(Wpost[k0 * W_ + col], Wpost[(k0 + 1) * W_ + col]);
        o.y = packh(Wpost[(k0 + 8) * W_ + col], Wpost[(k0 + 9) * W_ + col]);
        int stage = nt >> 3;
        g_wfph[((stage * 8 + (nt & 7)) * 32 + kt) * 32 + lane] = o;
        return;
    }
    b -= 128;
    float* ee_s = sbuf;
    int e0 = b * 32;
    if (tid < 128) s_attr[tid] = edge_attr[e0 * 4 + tid];
    float ew0 = __expf(init0_e[0]), ew1 = __expf(init0_e[1]);
    float ew2 = __expf(init0_e[2]), ew3 = __expf(init0_e[3]);
    float rs = rsqrtf(ew0 + ew1 + ew2 + ew3);
    ew0 *= rs; ew1 *= rs; ew2 *= rs; ew3 *= rs;
    __syncthreads();
    for (int idx = tid; idx < 32 * EW_; idx += 256) {
        int e = idx >> 7;
        int c = idx & (EW_ - 1);
        int a0 = s_attr[e * 4 + 0], a1 = s_attr[e * 4 + 1];
        int a2 = s_attr[e * 4 + 2], a3 = s_attr[e * 4 + 3];
        float v = emb0[a0 * EW_ + c] * ew0 + emb1[a1 * EW_ + c] * ew1 +
                  emb2[a2 * EW_ + c] * ew2 + emb3[a3 * EW_ + c] * ew3;
        ee_s[idx] = 0.5f * (v + edge_embed[(e0 + e) * EW_ + c]);
    }
    __syncthreads();
    unsigned* out = (unsigned*)(g_eefh + (size_t)b * 512);
    for (int idx = tid; idx < 2048; idx += 256) {
        int i = idx & 3;
        int t = (idx >> 2) & 31;
        int kt = (idx >> 7) & 7;
        int let = idx >> 10;
        int er = (t >> 2) + ((i & 1) << 3);
        int kc = kt * 16 + (t & 3) * 2 + ((i >> 1) << 3);
        out[idx] = packh(ee_s[(let * 16 + er) * EW_ + kc],
                         ee_s[(let * 16 + er) * EW_ + kc + 1]);
    }
}

// ---------------------------------------------------------------------------
// Tensorized pre: xx = LN(x@W_pre + b_pre), 64 nodes/block, fp16 mma.
// ---------------------------------------------------------------------------
__global__ void __launch_bounds__(256, 1) k_preT(const float* __restrict__ bpre) {
    extern __shared__ char dsm[];
    uint4* a_sm = (uint4*)dsm;               // 32KB
    uint2* b_sm = (uint2*)(dsm + 32768);     // 128KB (aliased by ys after mma)
    float* ys = (float*)(dsm + 32768);       // [64][256] = 64KB
    __shared__ float s_mean[64], s_rstd[64];
    __shared__ __align__(8) unsigned long long mbar_s[2];

    int tid = threadIdx.x;
    int lane = tid & 31, wid = tid >> 5;
    int mg = wid >> 2;
    int ng = wid & 3;
    int gid = lane >> 2, tg = lane & 3;
    int blk = blockIdx.x;

    unsigned mbA = s2u(&mbar_s[0]);
    unsigned mbB = s2u(&mbar_s[1]);
    if (tid == 0) {
        mbar_init(mbA, 1);
        mbar_init(mbB, 1);
    }
    __syncthreads();
    if (tid == 0) {
        mbar_expect(mbA, 32768);
        bulk_g2s(s2u(a_sm), g_xf + (size_t)blk * 2048, 32768, mbA);
        mbar_expect(mbB, 131072);
        bulk_g2s(s2u(b_sm), g_wfpre, 65536, mbB);
        bulk_g2s(s2u(b_sm + 8192), g_wfpre + 8192, 65536, mbB);
    }

    float acc[2][8][4];
#pragma unroll
    for (int mt = 0; mt < 2; mt++)
#pragma unroll
        for (int nt = 0; nt < 8; nt++)
#pragma unroll
            for (int c = 0; c < 4; c++) acc[mt][nt][c] = 0.f;

    const uint4* aw = a_sm + mg * 1024 + lane;
    const uint2* bw = b_sm + ng * 8 * 512 + lane;

    mbar_wait(mbA, 0);
    mbar_wait(mbB, 0);

#pragma unroll 4
    for (int kt = 0; kt < 16; kt++) {
        uint4 av0 = aw[kt * 32];
        uint4 av1 = aw[512 + kt * 32];
#pragma unroll
        for (int nt = 0; nt < 8; nt++) {
            uint2 bv = bw[nt * 512 + kt * 32];
            mma16(acc[0][nt], av0, bv);
            mma16(acc[1][nt], av1, bv);
        }
    }
    __syncthreads();  // done reading b_sm; safe to alias ys

#pragma unroll
    for (int mt = 0; mt < 2; mt++) {
        int r0 = (mg * 2 + mt) * 16 + gid;
        int r1 = r0 + 8;
#pragma unroll
        for (int nt = 0; nt < 8; nt++) {
            int c = ng * 64 + nt * 8 + tg * 2;
            float2 bb = *(const float2*)(bpre + c);
            ys[r0 * W_ + c] = acc[mt][nt][0] + bb.x;
            ys[r0 * W_ + c + 1] = acc[mt][nt][1] + bb.y;
            ys[r1 * W_ + c] = acc[mt][nt][2] + bb.x;
            ys[r1 * W_ + c + 1] = acc[mt][nt][3] + bb.y;
        }
    }
    __syncthreads();

#pragma unroll
    for (int rr = 0; rr < 8; rr++) {
        int row = wid * 8 + rr;
        float s = 0.f;
#pragma unroll
        for (int m = 0; m < W_ / 32; m++) s += ys[row * W_ + lane + 32 * m];
#pragma unroll
        for (int off = 16; off > 0; off >>= 1) s += __shfl_xor_sync(0xffffffffu, s, off);
        float mean = s * (1.0f / W_);
        float v = 0.f;
#pragma unroll
        for (int m = 0; m < W_ / 32; m++) {
            float d = ys[row * W_ + lane + 32 * m] - mean;
            v += d * d;
        }
#pragma unroll
        for (int off = 16; off > 0; off >>= 1) v += __shfl_xor_sync(0xffffffffu, v, off);
        if (lane == 0) {
            s_mean[row] = mean;
            s_rstd[row] = rsqrtf(v * (1.0f / W_) + 1e-5f);
        }
    }
    __syncthreads();

    unsigned* out = (unsigned*)(g_xxfh + (size_t)blk * 2048);
    for (int idx = tid; idx < 8192; idx += 256) {
        int w = idx & 2047;
        int tile = idx >> 11;
        int i = w & 3;
        int t = (w >> 2) & 31;
        int kt = w >> 7;
        int er = (t >> 2) + ((i & 1) << 3);
        int row = tile * 16 + er;
        int kc = kt * 16 + (t & 3) * 2 + ((i >> 1) << 3);
        float mean = s_mean[row], rstd = s_rstd[row];
        out[idx] = packh((ys[row * W_ + kc] - mean) * rstd,
                         (ys[row * W_ + kc + 1] - mean) * rstd);
    }
}

// ---------------------------------------------------------------------------
// fp16 node projections: qn/kn/vn stored as half2 (uint2 stores), m0 fp32.
// ---------------------------------------------------------------------------
__global__ void __launch_bounds__(256, 2) k_projz(const float* __restrict__ bq,
                                                  const float* __restrict__ bk,
                                                  const float* __restrict__ bv,
                                                  const float* __restrict__ bm,
                                                  const float* __restrict__ br0,
                                                  const float* __restrict__ br1,
                                                  const float* __restrict__ br2,
                                                  const float* __restrict__ init0) {
    extern __shared__ char dsm[];
    uint4* a_sm = (uint4*)dsm;               // 32KB
    uint2* b_sm = (uint2*)(dsm + 32768);     // 2 x 32KB
    __shared__ __align__(8) unsigned long long mbar_s[3];

    int tid = threadIdx.x;
    int lane = tid & 31, wid = tid >> 5;
    int mg = wid >> 2;
    int ng = wid & 3;
    int gid = lane >> 2, tg = lane & 3;
    int blk = blockIdx.x;

    unsigned mbA = s2u(&mbar_s[0]);
    unsigned mb0 = s2u(&mbar_s[1]);
    unsigned mb1 = s2u(&mbar_s[2]);
    if (tid == 0) {
        mbar_init(mbA, 1);
        mbar_init(mb0, 1);
        mbar_init(mb1, 1);
    }
    float s_e = __expf(init0[2]);
    float s_v = __expf(init0[3]);
    __syncthreads();

    if (tid == 0) {
        mbar_expect(mbA, 32768);
        bulk_g2s(s2u(a_sm), g_xxfh + (size_t)blk * 2048, 32768, mbA);
        mbar_expect(mb0, 32768);
        bulk_g2s(s2u(b_sm), g_wfnh, 32768, mb0);
        mbar_expect(mb1, 32768);
        bulk_g2s(s2u(b_sm + 4096), g_wfnh + 4096, 32768, mb1);
    }

    {
        int r0 = blk * 64;
        float4 z = make_float4(0.f, 0.f, 0.f, 0.f);
        for (int i = tid; i < 64 * (H_ / 4); i += 256) {
            int r = r0 + (i >> 7);
            if (r < NN) *(float4*)(g_agg + (size_t)r * H_ + ((i & 127) << 2)) = z;
        }
    }

    const uint4* aw = a_sm + mg * 1024 + lane;
    const uint2* bw = b_sm + (ng * 2) * 512 + lane;

    mbar_wait(mbA, 0);
    int ph0 = 0, ph1 = 0;

#pragma unroll 1
    for (int s = 0; s < 32; s++) {
        int buf = s & 1;
        if (buf == 0) { mbar_wait(mb0, ph0); ph0 ^= 1; }
        else          { mbar_wait(mb1, ph1); ph1 ^= 1; }

        float acc[2][2][4];
#pragma unroll
        for (int mt = 0; mt < 2; mt++)
#pragma unroll
            for (int nt = 0; nt < 2; nt++)
#pragma unroll
                for (int c = 0; c < 4; c++) acc[mt][nt][c] = 0.f;

#pragma unroll 4
        for (int kt = 0; kt < 16; kt++) {
            uint4 av0 = aw[kt * 32];
            uint4 av1 = aw[512 + kt * 32];
            uint2 bv0 = bw[buf * 4096 + kt * 32];
            uint2 bv1 = bw[buf * 4096 + 512 + kt * 32];
            mma16(acc[0][0], av0, bv0);
            mma16(acc[0][1], av0, bv1);
            mma16(acc[1][0], av1, bv0);
            mma16(acc[1][1], av1, bv1);
        }
        __syncthreads();
        if (tid == 0 && s + 2 < 32) {
            if (buf == 0) { mbar_expect(mb0, 32768); bulk_g2s(s2u(b_sm), g_wfnh + (size_t)(s + 2) * 4096, 32768, mb0); }
            else          { mbar_expect(mb1, 32768); bulk_g2s(s2u(b_sm + 4096), g_wfnh + (size_t)(s + 2) * 4096, 32768, mb1); }
        }

        int m = s >> 3, cc = s & 7;
        const float* bmain = (m == 0) ? bq : ((m == 1) ? bk : ((m == 2) ? bv : bm));
        const float* badd  = (m == 0) ? br0 : ((m == 1) ? br1 : br2);
        float scale = (m < 2) ? s_e : s_v;
        int col = cc * 64 + ng * 16 + tg * 4;
        float4 bb = *(const float4*)(bmain + col);
        if (m < 3) {
            float4 b2 = *(const float4*)(badd + col);
            bb = make_float4(bb.x + b2.x * scale, bb.y + b2.y * scale,
                             bb.z + b2.z * scale, bb.w + b2.w * scale);
        }
#pragma unroll
        for (int mt = 0; mt < 2; mt++) {
            int r0 = blk * 64 + mg * 32 + mt * 16 + gid;
            int r1 = r0 + 8;
            float4 o0 = make_float4(acc[mt][0][0] + bb.x, acc[mt][0][1] + bb.y,
                                    acc[mt][1][0] + bb.z, acc[mt][1][1] + bb.w);
            float4 o1 = make_float4(acc[mt][0][2] + bb.x, acc[mt][0][3] + bb.y,
                                    acc[mt][1][2] + bb.z, acc[mt][1][3] + bb.w);
            if (m == 3) {
                o0 = make_float4(gelu_fast(o0.x), gelu_fast(o0.y), gelu_fast(o0.z), gelu_fast(o0.w));
                o1 = make_float4(gelu_fast(o1.x), gelu_fast(o1.y), gelu_fast(o1.z), gelu_fast(o1.w));
                if (r0 < NN) *(float4*)(g_m0 + (size_t)r0 * H_ + col) = o0;
                if (r1 < NN) *(float4*)(g_m0 + (size_t)r1 * H_ + col) = o1;
            } else {
                __half* dsth = (m == 0) ? g_qnh : ((m == 1) ? g_knh : g_vnh);
                if (r0 < NN) *(uint2*)(dsth + (size_t)r0 * H_ + col) =
                    make_uint2(packh(o0.x, o0.y), packh(o0.z, o0.w));
                if (r1 < NN) *(uint2*)(dsth + (size_t)r1 * H_ + col) =
                    make_uint2(packh(o1.x, o1.y), packh(o1.z, o1.w));
            }
        }
    }
}

// ---------------------------------------------------------------------------
// fp16 edge kernel: 128 edges/block, 512 threads (4 mg x 4 ng).
// Champion R11 schedule; q/k/v gathers now 8B fp16 loads (half the sectors).
// ---------------------------------------------------------------------------
__global__ void __launch_bounds__(512) k_edge(const int* __restrict__ edge_index,
                                              const float* __restrict__ init0) {
    extern __shared__ char dsm[];
    uint4* a_sm = (uint4*)dsm;               // 32KB
    uint2* b_sm = (uint2*)(dsm + 32768);     // 2 x 48KB
    __shared__ int s_src[128], s_dst[128];
    __shared__ float p_buf[2][4][128];
    __shared__ __align__(8) unsigned long long mbar_s[3];

    int tid = threadIdx.x;
    int lane = tid & 31, wid = tid >> 5;
    int mg = wid >> 2;
    int ng = wid & 3;
    int gid = lane >> 2, tg = lane & 3;
    int e0 = blockIdx.x * 128;

    unsigned mbA = s2u(&mbar_s[0]);
    unsigned mb0 = s2u(&mbar_s[1]);
    unsigned mb1 = s2u(&mbar_s[2]);

    if (tid < 128) {
        s_src[tid] = edge_index[e0 + tid];
        s_dst[tid] = edge_index[NE + e0 + tid];
    }
    if (tid == 0) {
        mbar_init(mbA, 1);
        mbar_init(mb0, 1);
        mbar_init(mb1, 1);
    }
    float c0 = init0[0] * 0.125f;
    float c1 = init0[1];
    __syncthreads();

    if (tid == 0) {
        mbar_expect(mbA, 32768);
        bulk_g2s(s2u(a_sm), g_eefh + (size_t)blockIdx.x * 2048, 32768, mbA);
        mbar_expect(mb0, 49152);
        bulk_g2s(s2u(b_sm), g_wf2h, 49152, mb0);
        mbar_expect(mb1, 49152);
        bulk_g2s(s2u(b_sm + 6144), g_wf2h + 6144, 49152, mb1);
    }

    int rd0[2], rd1[2], rs0[2], rs1[2];
#pragma unroll
    for (int mt = 0; mt < 2; mt++) {
        int el = mg * 32 + mt * 16 + gid;
        rd0[mt] = s_dst[el];
        rd1[mt] = s_dst[el + 8];
        rs0[mt] = s_src[el];
        rs1[mt] = s_src[el + 8];
    }

    const uint4* aw = a_sm + mg * 512 + lane;
    const uint2* bw = b_sm + (ng * 2) * 256 + lane;

    mbar_wait(mbA, 0);
    int ph0 = 0, ph1 = 0;

#pragma unroll 1
    for (int chunk = 0; chunk < 8; chunk++) {
        float acc[3][2][2][4];
#pragma unroll
        for (int m = 0; m < 3; m++)
#pragma unroll
            for (int mt = 0; mt < 2; mt++)
#pragma unroll
                for (int nt = 0; nt < 2; nt++)
#pragma unroll
                    for (int c = 0; c < 4; c++) acc[m][mt][nt][c] = 0.f;

        int colbase = chunk * 64 + ng * 16 + tg * 4;
        int bufbase = (chunk & 1) * 6144;
        int pb = chunk & 1;

        // prefetch q/k gathers (fp16, 8B each)
        float4 qv[2][2], kv[2][2];
#pragma unroll
        for (int mt = 0; mt < 2; mt++) {
            qv[mt][0] = ldh4(g_qnh + (size_t)rd0[mt] * H_ + colbase);
            qv[mt][1] = ldh4(g_qnh + (size_t)rd1[mt] * H_ + colbase);
            kv[mt][0] = ldh4(g_knh + (size_t)rs0[mt] * H_ + colbase);
            kv[mt][1] = ldh4(g_knh + (size_t)rs1[mt] * H_ + colbase);
        }

        if ((chunk & 1) == 0) { mbar_wait(mb0, ph0); ph0 ^= 1; }
        else                  { mbar_wait(mb1, ph1); ph1 ^= 1; }

#pragma unroll
        for (int kt = 0; kt < 4; kt++) {
            uint4 av0 = aw[kt * 32];
            uint4 av1 = aw[256 + kt * 32];
            uint2 bv[3][2];
#pragma unroll
            for (int m = 0; m < 3; m++)
#pragma unroll
                for (int nt = 0; nt < 2; nt++)
                    bv[m][nt] = bw[bufbase + (m * 8 + nt) * 256 + kt * 32];
#pragma unroll
            for (int m = 0; m < 3; m++)
#pragma unroll
                for (int nt = 0; nt < 2; nt++) {
                    mma16(acc[m][0][nt], av0, bv[m][nt]);
                    mma16(acc[m][1][nt], av1, bv[m][nt]);
                }
        }

        // prefetch v gathers (hide under second mma half)
        float4 vv[2][2];
#pragma unroll
        for (int mt = 0; mt < 2; mt++) {
            vv[mt][0] = ldh4(g_vnh + (size_t)rs0[mt] * H_ + colbase);
            vv[mt][1] = ldh4(g_vnh + (size_t)rs1[mt] * H_ + colbase);
        }

#pragma unroll
        for (int kt = 4; kt < 8; kt++) {
            uint4 av0 = aw[kt * 32];
            uint4 av1 = aw[256 + kt * 32];
            uint2 bv[3][2];
#pragma unroll
            for (int m = 0; m < 3; m++)
#pragma unroll
                for (int nt = 0; nt < 2; nt++)
                    bv[m][nt] = bw[bufbase + (m * 8 + nt) * 256 + kt * 32];
#pragma unroll
            for (int m = 0; m < 3; m++)
#pragma unroll
                for (int nt = 0; nt < 2; nt++) {
                    mma16(acc[m][0][nt], av0, bv[m][nt]);
                    mma16(acc[m][1][nt], av1, bv[m][nt]);
                }
        }

        float p[2][2];
#pragma unroll
        for (int mt = 0; mt < 2; mt++) {
            p[mt][0] = (qv[mt][0].x + acc[0][mt][0][0]) * (kv[mt][0].x + acc[1][mt][0][0])
                     + (qv[mt][0].y + acc[0][mt][0][1]) * (kv[mt][0].y + acc[1][mt][0][1])
                     + (qv[mt][0].z + acc[0][mt][1][0]) * (kv[mt][0].z + acc[1][mt][1][0])
                     + (qv[mt][0].w + acc[0][mt][1][1]) * (kv[mt][0].w + acc[1][mt][1][1]);
            p[mt][1] = (qv[mt][1].x + acc[0][mt][0][2]) * (kv[mt][1].x + acc[1][mt][0][2])
                     + (qv[mt][1].y + acc[0][mt][0][3]) * (kv[mt][1].y + acc[1][mt][0][3])
                     + (qv[mt][1].z + acc[0][mt][1][2]) * (kv[mt][1].z + acc[1][mt][1][2])
                     + (qv[mt][1].w + acc[0][mt][1][3]) * (kv[mt][1].w + acc[1][mt][1][3]);
        }
#pragma unroll
        for (int off = 1; off <= 2; off <<= 1) {
            p[0][0] += __shfl_xor_sync(0xffffffffu, p[0][0], off);
            p[0][1] += __shfl_xor_sync(0xffffffffu, p[0][1], off);
            p[1][0] += __shfl_xor_sync(0xffffffffu, p[1][0], off);
            p[1][1] += __shfl_xor_sync(0xffffffffu, p[1][1], off);
        }
        if (tg == 0) {
#pragma unroll
            for (int mt = 0; mt < 2; mt++) {
                int el = mg * 32 + mt * 16 + gid;
                p_buf[pb][ng][el] = p[mt][0];
                p_buf[pb][ng][el + 8] = p[mt][1];
            }
        }
        __syncthreads();   // pbuf write->read; also all warps done with B buf
        if (tid == 0 && chunk < 6) {
            if ((chunk & 1) == 0) { mbar_expect(mb0, 49152); bulk_g2s(s2u(b_sm), g_wf2h + (size_t)(chunk + 2) * 6144, 49152, mb0); }
            else                  { mbar_expect(mb1, 49152); bulk_g2s(s2u(b_sm + 6144), g_wf2h + (size_t)(chunk + 2) * 6144, 49152, mb1); }
        }

#pragma unroll
        for (int mt = 0; mt < 2; mt++) {
            int el = mg * 32 + mt * 16 + gid;
            float sum0 = p_buf[pb][0][el] + p_buf[pb][1][el] + p_buf[pb][2][el] + p_buf[pb][3][el];
            float sum1 = p_buf[pb][0][el + 8] + p_buf[pb][1][el + 8] + p_buf[pb][2][el + 8] + p_buf[pb][3][el + 8];
            float att0 = __expf(sum0 * c0 + c1);
            float att1 = __expf(sum1 * c0 + c1);
            red4(g_agg + (size_t)rd0[mt] * H_ + colbase,
                 gelu_fast(vv[mt][0].x + acc[2][mt][0][0]) * att0,
                 gelu_fast(vv[mt][0].y + acc[2][mt][0][1]) * att0,
                 gelu_fast(vv[mt][0].z + acc[2][mt][1][0]) * att0,
                 gelu_fast(vv[mt][0].w + acc[2][mt][1][1]) * att0);
            red4(g_agg + (size_t)rd1[mt] * H_ + colbase,
                 gelu_fast(vv[mt][1].x + acc[2][mt][0][2]) * att1,
                 gelu_fast(vv[mt][1].y + acc[2][mt][0][3]) * att1,
                 gelu_fast(vv[mt][1].z + acc[2][mt][1][2]) * att1,
                 gelu_fast(vv[mt][1].w + acc[2][mt][1][3]) * att1);
        }
    }
}

// ---------------------------------------------------------------------------
// fp16 post kernel: out = x + (m0+agg) @ W_post + b_post. float4 A-build.
// ---------------------------------------------------------------------------
__global__ void __launch_bounds__(256) k_post(const float* __restrict__ x,
                                              const float* __restrict__ bp,
                                              float* __restrict__ out) {
    extern __shared__ char dsm[];
    uint4* a_sm = (uint4*)dsm;               // 64KB
    uint2* b_sm = (uint2*)(dsm + 65536);     // 2 x 64KB
    __shared__ __align__(8) unsigned long long mbar_s[2];

    int tid = threadIdx.x;
    int lane = tid & 31, wid = tid >> 5;
    int mg = wid >> 2;
    int ng = wid & 3;
    int gid = lane >> 2, tg = lane & 3;
    int blk = blockIdx.x;

    unsigned mb0 = s2u(&mbar_s[0]);
    unsigned mb1 = s2u(&mbar_s[1]);
    if (tid == 0) {
        mbar_init(mb0, 1);
        mbar_init(mb1, 1);
    }
    __syncthreads();
    if (tid == 0) {
        mbar_expect(mb0, 65536);
        bulk_g2s(s2u(b_sm), g_wfph, 65536, mb0);
        mbar_expect(mb1, 65536);
        bulk_g2s(s2u(b_sm + 8192), g_wfph + 8192, 65536, mb1);
    }

    {
        unsigned* aword = (unsigned*)a_sm;
        for (int idx = tid; idx < 8192; idx += 256) {
            int rl = idx >> 7;
            int c4 = (idx & 127) << 2;
            int row = blk * 64 + rl;
            float4 f = make_float4(0.f, 0.f, 0.f, 0.f);
            if (row < NN) {
                float4 m4 = *(const float4*)(g_m0 + (size_t)row * H_ + c4);
                float4 a4 = *(const float4*)(g_agg + (size_t)row * H_ + c4);
                f = make_float4(m4.x + a4.x, m4.y + a4.y, m4.z + a4.z, m4.w + a4.w);
            }
            int mt = rl >> 4;
            int er = rl & 15;
            int kt = c4 >> 4;
            int i = (er >> 3) | (((c4 >> 3) & 1) << 1);
            int tb = (er & 7) * 4 + ((c4 >> 1) & 3);
            int base = ((mt * 32 + kt) * 32 + tb) * 4 + i;
            aword[base] = packh(f.x, f.y);
            aword[base + 4] = packh(f.z, f.w);
        }
    }
    __syncthreads();

    const uint4* aw = a_sm + mg * 2048 + lane;
    const uint2* bw = b_sm + (ng * 2) * 1024 + lane;
    int ph0 = 0, ph1 = 0;

#pragma unroll 1
    for (int s = 0; s < 4; s++) {
        int buf = s & 1;
        if (buf == 0) { mbar_wait(mb0, ph0); ph0 ^= 1; }
        else          { mbar_wait(mb1, ph1); ph1 ^= 1; }

        float acc[2][2][4];
#pragma unroll
        for (int mt = 0; mt < 2; mt++)
#pragma unroll
            for (int nt = 0; nt < 2; nt++)
#pragma unroll
                for (int c = 0; c < 4; c++) acc[mt][nt][c] = 0.f;

#pragma unroll 4
        for (int kt = 0; kt < 32; kt++) {
            uint4 av0 = aw[kt * 32];
            uint4 av1 = aw[1024 + kt * 32];
            uint2 bv0 = bw[buf * 8192 + kt * 32];
            uint2 bv1 = bw[buf * 8192 + 1024 + kt * 32];
            mma16(acc[0][0], av0, bv0);
            mma16(acc[0][1], av0, bv1);
            mma16(acc[1][0], av1, bv0);
            mma16(acc[1][1], av1, bv1);
        }
        __syncthreads();
        if (tid == 0 && s + 2 < 4) {
            if (buf == 0) { mbar_expect(mb0, 65536); bulk_g2s(s2u(b_sm), g_wfph + (size_t)(s + 2) * 8192, 65536, mb0); }
            else          { mbar_expect(mb1, 65536); bulk_g2s(s2u(b_sm + 8192), g_wfph + (size_t)(s + 2) * 8192, 65536, mb1); }
        }

        int col = s * 64 + ng * 16 + tg * 4;
        float4 bb = *(const float4*)(bp + col);
#pragma unroll
        for (int mt = 0; mt < 2; mt++) {
            int r0 = blk * 64 + mg * 32 + mt * 16 + gid;
            int r1 = r0 + 8;
            if (r0 < NN) {
                float4 xx0 = *(const float4*)(x + (size_t)r0 * W_ + col);
                *(float4*)(out + (size_t)r0 * W_ + col) =
                    make_float4(xx0.x + acc[mt][0][0] + bb.x, xx0.y + acc[mt][0][1] + bb.y,
                                xx0.z + acc[mt][1][0] + bb.z, xx0.w + acc[mt][1][1] + bb.w);
            }
            if (r1 < NN) {
                float4 xx1 = *(const float4*)(x + (size_t)r1 * W_ + col);
                *(float4*)(out + (size_t)r1 * W_ + col) =
                    make_float4(xx1.x + acc[mt][0][2] + bb.x, xx1.y + acc[mt][0][3] + bb.y,
                                xx1.z + acc[mt][1][2] + bb.z, xx1.w + acc[mt][1][3] + bb.w);
            }
        }
    }
}

extern "C" void kernel_launch(void* const* d_in, const int* in_sizes, int n_in,
                              void* d_out, int out_size) {
    const float* x          = (const float*)d_in[0];
    const int*   edge_index = (const int*)d_in[1];
    const int*   edge_attr  = (const int*)d_in[2];
    const float* edge_embed = (const float*)d_in[3];
    const float* emb0       = (const float*)d_in[4];
    const float* emb1       = (const float*)d_in[5];
    const float* emb2       = (const float*)d_in[6];
    const float* emb3       = (const float*)d_in[7];
    const float* init0_e    = (const float*)d_in[8];
    const float* init0      = (const float*)d_in[9];
    const float* W_pre      = (const float*)d_in[10];
    const float* b_pre      = (const float*)d_in[11];
    const float* W_msg0     = (const float*)d_in[12];
    const float* b_msg0     = (const float*)d_in[13];
    const float* W_q        = (const float*)d_in[14];
    const float* b_q        = (const float*)d_in[15];
    const float* W_k        = (const float*)d_in[16];
    const float* b_k        = (const float*)d_in[17];
    const float* W_v        = (const float*)d_in[18];
    const float* b_v        = (const float*)d_in[19];
    const float* W_r0       = (const float*)d_in[20];
    const float* b_r0       = (const float*)d_in[21];
    const float* W_r1       = (const float*)d_in[22];
    const float* b_r1       = (const float*)d_in[23];
    const float* W_r2       = (const float*)d_in[24];
    const float* b_r2       = (const float*)d_in[25];
    const float* W_post     = (const float*)d_in[26];
    const float* b_post     = (const float*)d_in[27];
    float* out = (float*)d_out;

    cudaFuncSetAttribute(k_edge, cudaFuncAttributeMaxDynamicSharedMemorySize, 131072);
    cudaFuncSetAttribute(k_projz, cudaFuncAttributeMaxDynamicSharedMemorySize, 98304);
    cudaFuncSetAttribute(k_post, cudaFuncAttributeMaxDynamicSharedMemorySize, 196608);
    cudaFuncSetAttribute(k_preT, cudaFuncAttributeMaxDynamicSharedMemorySize, 163840);

    k_wfeef<<<1524 + NE / 32, 256>>>(x, W_pre,
                                     W_r0, W_r1, W_r2, W_q, W_k, W_v, W_msg0, W_post,
                                     edge_attr, edge_embed,
                                     emb0, emb1, emb2, emb3, init0_e, init0);
    k_preT<<<NP / 64, 256, 163840>>>(b_pre);
    k_projz<<<NP / 64, 256, 98304>>>(b_q, b_k, b_v, b_msg0, b_r0, b_r1, b_r2, init0);
    k_edge<<<NE / 128, 512, 131072>>>(edge_index, init0);
    k_post<<<NP / 64, 256, 196608>>>(x, b_post, out);
}